// round 1
// baseline (speedup 1.0000x reference)
#include <cuda_runtime.h>
#include <cuda_bf16.h>
#include <math.h>

// Problem constants
#define NB   64
#define NI   1024
#define NHID 2048
#define NH   8
#define ND   256
#define EPS  1e-5f

// ---------------- device scratch (no allocations allowed) ----------------
__device__ float g_xn[NB * NI];
__device__ float g_xl[NB * NHID];
__device__ float g_xr[NB * NHID];
__device__ float g_xc[NB * NHID];
__device__ float g_xskip[NB * NHID];
__device__ float g_o[NB * NHID];
__device__ float g_q[NB * NHID];
__device__ float g_k[NB * NHID];
__device__ float g_v[NB * NHID];
__device__ float g_outpre[NB * NHID];
__device__ float g_ig[NB * NH];
__device__ float g_fg[NB * NH];
__device__ float g_part[16 * NB * NHID];   // split-K partial buffers (16 slots)

// ---------------- helpers ----------------
__device__ __forceinline__ float blockReduce256(float v) {
    __shared__ float red[256];
    int t = threadIdx.x;
    red[t] = v;
    __syncthreads();
#pragma unroll
    for (int s = 128; s > 0; s >>= 1) {
        if (t < s) red[t] += red[t + s];
        __syncthreads();
    }
    float r = red[0];
    __syncthreads();
    return r;
}

__device__ __forceinline__ float sigmoidf_(float x) { return 1.f / (1.f + expf(-x)); }
__device__ __forceinline__ float siluf_(float x) { return x / (1.f + expf(-x)); }

// ---------------- LayerNorm: x[64,1024] -> g_xn ----------------
__global__ __launch_bounds__(256) void ln_kernel(const float* __restrict__ x,
                                                 const float* __restrict__ w,
                                                 const float* __restrict__ b) {
    int bi = blockIdx.x, t = threadIdx.x;
    const float* xr = x + bi * NI;
    float vals[4];
    float s = 0.f;
#pragma unroll
    for (int i = 0; i < 4; i++) { vals[i] = xr[t + 256 * i]; s += vals[i]; }
    float mu = blockReduce256(s) * (1.f / NI);
    float s2 = 0.f;
#pragma unroll
    for (int i = 0; i < 4; i++) { float d = vals[i] - mu; s2 += d * d; }
    float var = blockReduce256(s2) * (1.f / NI);
    float rs = rsqrtf(var + EPS);
#pragma unroll
    for (int i = 0; i < 4; i++) {
        int c = t + 256 * i;
        g_xn[bi * NI + c] = (vals[i] - mu) * rs * w[c] + b[c];
    }
}

// ---------------- generic split-K GEMM partial: C_part = A[64,K] @ W[K,N] ----------------
// grid.x = N/64 tile, grid.y = k-split. Writes partial (no bias/act).
__global__ __launch_bounds__(256) void gemm_part(const float* __restrict__ A,
                                                 const float* __restrict__ W,
                                                 float* __restrict__ P,
                                                 int K, int N, int kc) {
    int n0 = blockIdx.x * 64;
    int k0 = blockIdx.y * kc;
    int kend = min(k0 + kc, K);
    float* Pp = P + (size_t)blockIdx.y * 64 * N;
    __shared__ float As[32][65];
    __shared__ float Ws[32][65];
    int tx = threadIdx.x & 15, ty = threadIdx.x >> 4;
    float acc[4][4] = {};
    for (int kb = k0; kb < kend; kb += 32) {
#pragma unroll
        for (int e = threadIdx.x; e < 64 * 32; e += 256) {
            int m = e >> 5, k = e & 31;
            As[k][m] = A[m * K + kb + k];
        }
#pragma unroll
        for (int e = threadIdx.x; e < 32 * 64; e += 256) {
            int k = e >> 6, n = e & 63;
            Ws[k][n] = W[(size_t)(kb + k) * N + n0 + n];
        }
        __syncthreads();
#pragma unroll
        for (int kk = 0; kk < 32; kk++) {
            float a[4], w[4];
#pragma unroll
            for (int i = 0; i < 4; i++) a[i] = As[kk][ty * 4 + i];
#pragma unroll
            for (int j = 0; j < 4; j++) w[j] = Ws[kk][tx * 4 + j];
#pragma unroll
            for (int i = 0; i < 4; i++)
#pragma unroll
                for (int j = 0; j < 4; j++) acc[i][j] += a[i] * w[j];
        }
        __syncthreads();
    }
#pragma unroll
    for (int i = 0; i < 4; i++) {
        int m = ty * 4 + i;
#pragma unroll
        for (int j = 0; j < 4; j++) Pp[m * N + n0 + tx * 4 + j] = acc[i][j];
    }
}

// ---------------- conv GEMM partial: xc_pre[b,j] = sum_i xl[b,i]*W_conv[j,i,KS-1] ----------------
// W_conv is [2048,2048,4] -> read float4, take .w (tap 3). K=N=2048 fixed.
__global__ __launch_bounds__(256) void conv_gemm_part(const float* __restrict__ A,
                                                      const float* __restrict__ Wc,
                                                      float* __restrict__ P, int kc) {
    const float4* W4 = (const float4*)Wc;
    int n0 = blockIdx.x * 64;
    int k0 = blockIdx.y * kc;
    int kend = min(k0 + kc, NHID);
    float* Pp = P + (size_t)blockIdx.y * 64 * NHID;
    __shared__ float As[32][65];
    __shared__ float Ws[32][65];
    int tx = threadIdx.x & 15, ty = threadIdx.x >> 4;
    float acc[4][4] = {};
    for (int kb = k0; kb < kend; kb += 32) {
#pragma unroll
        for (int e = threadIdx.x; e < 64 * 32; e += 256) {
            int m = e >> 5, k = e & 31;
            As[k][m] = A[m * NHID + kb + k];
        }
        // W'[k][n] = Wc[n, k, 3]; consecutive threads scan k (contiguous float4s)
#pragma unroll
        for (int e = threadIdx.x; e < 32 * 64; e += 256) {
            int n = e >> 5, k = e & 31;
            Ws[k][n] = W4[(size_t)(n0 + n) * NHID + kb + k].w;
        }
        __syncthreads();
#pragma unroll
        for (int kk = 0; kk < 32; kk++) {
            float a[4], w[4];
#pragma unroll
            for (int i = 0; i < 4; i++) a[i] = As[kk][ty * 4 + i];
#pragma unroll
            for (int j = 0; j < 4; j++) w[j] = Ws[kk][tx * 4 + j];
#pragma unroll
            for (int i = 0; i < 4; i++)
#pragma unroll
                for (int j = 0; j < 4; j++) acc[i][j] += a[i] * w[j];
        }
        __syncthreads();
    }
#pragma unroll
    for (int i = 0; i < 4; i++) {
        int m = ty * 4 + i;
#pragma unroll
        for (int j = 0; j < 4; j++) Pp[m * NHID + n0 + tx * 4 + j] = acc[i][j];
    }
}

// ---------------- split-K reduce + epilogue ----------------
// mode: 0 = bias, 1 = silu(bias+), 2 = sigmoid(bias+), 3 = bias + residual R
__global__ __launch_bounds__(256) void reduce_ep(const float* __restrict__ P, int nparts,
                                                 const float* __restrict__ bias, int N,
                                                 float* __restrict__ C, int mode,
                                                 const float* __restrict__ R) {
    int idx = blockIdx.x * 256 + threadIdx.x;
    if (idx >= 64 * N) return;
    int n = idx % N;
    float s = 0.f;
    for (int p = 0; p < nparts; p++) s += P[(size_t)p * 64 * N + idx];
    s += bias[n];
    if (mode == 1) s = siluf_(s);
    else if (mode == 2) s = sigmoidf_(s);
    else if (mode == 3) s += R[idx];
    C[idx] = s;
}

// ---------------- block-diagonal q/k/v GEMMs ----------------
// grid: (4 n-tiles, 8 heads, 3 which). which: 0=q(xc), 1=k(xc, /16), 2=v(xl)
__global__ __launch_bounds__(256) void qkv_kernel(const float* __restrict__ Wq,
                                                  const float* __restrict__ Wk,
                                                  const float* __restrict__ Wv,
                                                  const float* __restrict__ bq,
                                                  const float* __restrict__ bk,
                                                  const float* __restrict__ bv) {
    int h = blockIdx.y, which = blockIdx.z;
    const float* A = (which == 2) ? g_xl : g_xc;
    const float* W;
    const float* bias;
    float* C;
    float scale = 1.f;
    if (which == 0) { W = Wq; bias = bq; C = g_q; }
    else if (which == 1) { W = Wk; bias = bk; C = g_k; scale = 0.0625f; }
    else { W = Wv; bias = bv; C = g_v; }
    W += (size_t)h * ND * ND;
    bias += h * ND;
    int n0 = blockIdx.x * 64;
    __shared__ float As[32][65];
    __shared__ float Ws[32][65];
    int tx = threadIdx.x & 15, ty = threadIdx.x >> 4;
    float acc[4][4] = {};
    for (int kb = 0; kb < ND; kb += 32) {
#pragma unroll
        for (int e = threadIdx.x; e < 64 * 32; e += 256) {
            int m = e >> 5, k = e & 31;
            As[k][m] = A[m * NHID + h * ND + kb + k];
        }
#pragma unroll
        for (int e = threadIdx.x; e < 32 * 64; e += 256) {
            int k = e >> 6, n = e & 63;
            Ws[k][n] = W[(kb + k) * ND + n0 + n];
        }
        __syncthreads();
#pragma unroll
        for (int kk = 0; kk < 32; kk++) {
            float a[4], w[4];
#pragma unroll
            for (int i = 0; i < 4; i++) a[i] = As[kk][ty * 4 + i];
#pragma unroll
            for (int j = 0; j < 4; j++) w[j] = Ws[kk][tx * 4 + j];
#pragma unroll
            for (int i = 0; i < 4; i++)
#pragma unroll
                for (int j = 0; j < 4; j++) acc[i][j] += a[i] * w[j];
        }
        __syncthreads();
    }
#pragma unroll
    for (int i = 0; i < 4; i++) {
        int m = ty * 4 + i;
#pragma unroll
        for (int j = 0; j < 4; j++) {
            int n = n0 + tx * 4 + j;
            C[m * NHID + h * ND + n] = (acc[i][j] + bias[n]) * scale;
        }
    }
}

// ---------------- i/f gate GEMVs + stabilized exp gating ----------------
__global__ __launch_bounds__(256) void gates_kernel(const float* __restrict__ Wi,
                                                    const float* __restrict__ bi,
                                                    const float* __restrict__ Wf,
                                                    const float* __restrict__ bf,
                                                    const float* __restrict__ m_prev,
                                                    float* __restrict__ m_out) {
    int b = blockIdx.x, t = threadIdx.x;
    float pi[8] = {}, pf[8] = {};
    for (int k = t; k < NHID; k += 256) {
        float xv = g_xc[b * NHID + k];
        const float4* wi4 = (const float4*)(Wi + k * 8);
        const float4* wf4 = (const float4*)(Wf + k * 8);
        float4 a0 = wi4[0], a1 = wi4[1], f0 = wf4[0], f1 = wf4[1];
        pi[0] += xv * a0.x; pi[1] += xv * a0.y; pi[2] += xv * a0.z; pi[3] += xv * a0.w;
        pi[4] += xv * a1.x; pi[5] += xv * a1.y; pi[6] += xv * a1.z; pi[7] += xv * a1.w;
        pf[0] += xv * f0.x; pf[1] += xv * f0.y; pf[2] += xv * f0.z; pf[3] += xv * f0.w;
        pf[4] += xv * f1.x; pf[5] += xv * f1.y; pf[6] += xv * f1.z; pf[7] += xv * f1.w;
    }
    __shared__ float s[256 * 16];
#pragma unroll
    for (int h = 0; h < 8; h++) { s[t * 16 + h] = pi[h]; s[t * 16 + 8 + h] = pf[h]; }
    __syncthreads();
    if (t < 16) {
        float a = 0.f;
        for (int r = 0; r < 256; r++) a += s[r * 16 + t];
        s[t] = a;
    }
    __syncthreads();
    if (t < 8) {
        float it = s[t] + bi[t];
        float ft = s[8 + t] + bf[t];
        float mp = m_prev[b * 8 + t];
        float m = fmaxf(ft + mp, it);
        m_out[b * 8 + t] = m;
        g_ig[b * 8 + t] = expf(it - m);
        g_fg[b * 8 + t] = expf(ft + mp - m);
    }
}

// ---------------- fused state update + readout + GroupNorm + gating ----------------
// one block per (b,h). Touches c_prev/c_t exactly once each.
__global__ __launch_bounds__(256) void state_kernel(const float* __restrict__ c_prev,
                                                    const float* __restrict__ n_prev,
                                                    const float* __restrict__ gn_w,
                                                    const float* __restrict__ gn_b,
                                                    float* __restrict__ c_out,
                                                    float* __restrict__ n_out,
                                                    float* __restrict__ h_out) {
    int bh = blockIdx.x;
    int b = bh >> 3, h = bh & 7;
    int t = threadIdx.x;
    __shared__ __align__(16) float qs[256], ks[256], vs[256], hts[256];
    __shared__ float den_s;
    float fg = g_fg[bh], ig = g_ig[bh];
    int base = bh * ND;
    float qv = g_q[base + t], kv = g_k[base + t], vv = g_v[base + t];
    qs[t] = qv; ks[t] = kv; vs[t] = vv;
    float nt = fg * n_prev[base + t] + ig * kv;
    n_out[base + t] = nt;
    float den = blockReduce256(nt * qv);
    if (t == 0) den_s = fmaxf(den, 1.f);
    __syncthreads();
    den = den_s;
    int w = t >> 5, lane = t & 31;
    const float4* cp4 = (const float4*)(c_prev + (size_t)bh * ND * ND);
    float4* ct4 = (float4*)(c_out + (size_t)bh * ND * ND);
    const float4* qs4 = (const float4*)qs;
    const float4* ks4 = (const float4*)ks;
    for (int d = w; d < ND; d += 8) {
        float vd = vs[d] * ig;
        float acc = 0.f;
#pragma unroll
        for (int p = 0; p < 2; p++) {
            int ci = lane + p * 32;           // float4 col index 0..63
            float4 cp = cp4[d * 64 + ci];
            float4 kk = ks4[ci];
            float4 qq = qs4[ci];
            float4 ct;
            ct.x = fg * cp.x + vd * kk.x;
            ct.y = fg * cp.y + vd * kk.y;
            ct.z = fg * cp.z + vd * kk.z;
            ct.w = fg * cp.w + vd * kk.w;
            ct4[d * 64 + ci] = ct;
            acc += ct.x * qq.x + ct.y * qq.y + ct.z * qq.z + ct.w * qq.w;
        }
#pragma unroll
        for (int off = 16; off > 0; off >>= 1) acc += __shfl_xor_sync(0xffffffffu, acc, off);
        if (lane == 0) {
            float ov = g_o[base + d];
            float ht = ov * acc / den;
            hts[d] = ht;
            h_out[base + d] = ht;
        }
    }
    __syncthreads();
    // GroupNorm per head over D=256, then (gn + x_skip) * silu(xr)
    float hv = hts[t];
    float mu = blockReduce256(hv) * (1.f / ND);
    float dv = hv - mu;
    float var = blockReduce256(dv * dv) * (1.f / ND);
    float g = dv * rsqrtf(var + EPS);
    int hid = h * ND + t;
    float xrv = g_xr[b * NHID + hid];
    g_outpre[b * NHID + hid] =
        (g * gn_w[hid] + gn_b[hid] + g_xskip[b * NHID + hid]) * siluf_(xrv);
}

// ---------------- host launcher ----------------
extern "C" void kernel_launch(void* const* d_in, const int* in_sizes, int n_in,
                              void* d_out, int out_size) {
    (void)in_sizes; (void)n_in; (void)out_size;
    const float* x      = (const float*)d_in[0];
    // d_in[1] = h_prev (unused by reference)
    const float* c_prev = (const float*)d_in[2];
    const float* n_prev = (const float*)d_in[3];
    const float* m_prev = (const float*)d_in[4];
    const float* ln_w   = (const float*)d_in[5];
    const float* ln_b   = (const float*)d_in[6];
    const float* W_ul   = (const float*)d_in[7];
    const float* b_ul   = (const float*)d_in[8];
    const float* W_ur   = (const float*)d_in[9];
    const float* b_ur   = (const float*)d_in[10];
    const float* W_conv = (const float*)d_in[11];
    const float* b_conv = (const float*)d_in[12];
    const float* W_skip = (const float*)d_in[13];
    const float* b_skip = (const float*)d_in[14];
    const float* W_q    = (const float*)d_in[15];
    const float* b_q    = (const float*)d_in[16];
    const float* W_k    = (const float*)d_in[17];
    const float* b_k    = (const float*)d_in[18];
    const float* W_v    = (const float*)d_in[19];
    const float* b_v    = (const float*)d_in[20];
    const float* W_i    = (const float*)d_in[21];
    const float* b_i    = (const float*)d_in[22];
    const float* W_f    = (const float*)d_in[23];
    const float* b_f    = (const float*)d_in[24];
    const float* W_o    = (const float*)d_in[25];
    const float* b_o    = (const float*)d_in[26];
    const float* W_down = (const float*)d_in[27];
    const float* b_down = (const float*)d_in[28];
    const float* gn_w   = (const float*)d_in[29];
    const float* gn_b   = (const float*)d_in[30];

    float* out = (float*)d_out;
    float* out_final = out;                               // 64*1024
    float* out_h = out + NB * NI;                         // 64*8*256
    float* out_c = out_h + NB * NH * ND;                  // 64*8*256*256
    float* out_n = out_c + (size_t)NB * NH * ND * ND;     // 64*8*256
    float* out_m = out_n + NB * NH * ND;                  // 64*8

    // scratch symbol addresses
    void *p_xn, *p_xl, *p_xr, *p_xc, *p_xskip, *p_o, *p_outpre, *p_part;
    cudaGetSymbolAddress(&p_xn, g_xn);
    cudaGetSymbolAddress(&p_xl, g_xl);
    cudaGetSymbolAddress(&p_xr, g_xr);
    cudaGetSymbolAddress(&p_xc, g_xc);
    cudaGetSymbolAddress(&p_xskip, g_xskip);
    cudaGetSymbolAddress(&p_o, g_o);
    cudaGetSymbolAddress(&p_outpre, g_outpre);
    cudaGetSymbolAddress(&p_part, g_part);
    float* xn = (float*)p_xn;
    float* xl = (float*)p_xl;
    float* xr = (float*)p_xr;
    float* xc = (float*)p_xc;
    float* xskip = (float*)p_xskip;
    float* o = (float*)p_o;
    float* outpre = (float*)p_outpre;
    float* part = (float*)p_part;
    float* part8 = part + (size_t)8 * NB * NHID;

    const int SLOT = NB * NHID;

    // 1. LayerNorm
    ln_kernel<<<NB, 256>>>(x, ln_w, ln_b);
    // 2. xl = xn@W_ul, xr = xn@W_ur  (K=1024, N=2048, 4-way split-K each)
    gemm_part<<<dim3(32, 4), 256>>>(xn, W_ul, part, NI, NHID, 256);
    gemm_part<<<dim3(32, 4), 256>>>(xn, W_ur, part + (size_t)4 * SLOT, NI, NHID, 256);
    reduce_ep<<<512, 256>>>(part, 4, b_ul, NHID, xl, 0, nullptr);
    reduce_ep<<<512, 256>>>(part + (size_t)4 * SLOT, 4, b_ur, NHID, xr, 0, nullptr);
    // 3. conv (xc = silu(xl @ Wc3^T)), o-pre (xl @ W_o) — both depend on xl only
    conv_gemm_part<<<dim3(32, 8), 256>>>(xl, W_conv, part, 256);
    gemm_part<<<dim3(32, 8), 256>>>(xl, W_o, part8, NHID, NHID, 256);
    reduce_ep<<<512, 256>>>(part, 8, b_conv, NHID, xc, 1, nullptr);   // silu -> xc
    // 4. xc consumers + o reduce
    gemm_part<<<dim3(32, 8), 256>>>(xc, W_skip, part, NHID, NHID, 256);
    qkv_kernel<<<dim3(4, 8, 3), 256>>>(W_q, W_k, W_v, b_q, b_k, b_v);
    gates_kernel<<<NB, 256>>>(W_i, b_i, W_f, b_f, m_prev, out_m);
    reduce_ep<<<512, 256>>>(part8, 8, b_o, NHID, o, 2, nullptr);      // sigmoid -> o
    reduce_ep<<<512, 256>>>(part, 8, b_skip, NHID, xskip, 0, nullptr);
    // 5. fused state update / readout / groupnorm / gating
    state_kernel<<<NB * NH, 256>>>(c_prev, n_prev, gn_w, gn_b, out_c, out_n, out_h);
    // 6. final = outpre @ W_down + b_down + x
    gemm_part<<<dim3(16, 8), 256>>>(outpre, W_down, part, NHID, NI, 256);
    reduce_ep<<<256, 256>>>(part, 8, b_down, NI, out_final, 3, x);
}

// round 2
// speedup vs baseline: 1.3852x; 1.3852x over previous
#include <cuda_runtime.h>
#include <cuda_bf16.h>
#include <math.h>

#define NB   64
#define NI   1024
#define NHID 2048
#define NH   8
#define ND   256
#define EPS  1e-5f

// ---------------- device scratch ----------------
__device__ float g_xn[NB * NI];
__device__ float g_xl[NB * NHID];
__device__ float g_xr[NB * NHID];
__device__ float g_xc[NB * NHID];
__device__ float g_xskip[NB * NHID];
__device__ float g_o[NB * NHID];
__device__ float g_q[NB * NHID];
__device__ float g_k[NB * NHID];
__device__ float g_v[NB * NHID];
__device__ float g_outpre[NB * NHID];
__device__ float g_ig[NB * NH];
__device__ float g_fg[NB * NH];
__device__ float g_part[16 * NB * NHID];   // 16 split-K partial slots (8MB)

// ---------------- helpers ----------------
__device__ __forceinline__ float blockReduce256(float v) {
    __shared__ float red[256];
    int t = threadIdx.x;
    red[t] = v;
    __syncthreads();
#pragma unroll
    for (int s = 128; s > 0; s >>= 1) {
        if (t < s) red[t] += red[t + s];
        __syncthreads();
    }
    float r = red[0];
    __syncthreads();
    return r;
}
__device__ __forceinline__ float sigmoidf_(float x) { return 1.f / (1.f + expf(-x)); }
__device__ __forceinline__ float siluf_(float x) { return x / (1.f + expf(-x)); }

// ---------------- LayerNorm ----------------
__global__ __launch_bounds__(256) void ln_kernel(const float* __restrict__ x,
                                                 const float* __restrict__ w,
                                                 const float* __restrict__ b) {
    int bi = blockIdx.x, t = threadIdx.x;
    const float* xr = x + bi * NI;
    float vals[4];
    float s = 0.f;
#pragma unroll
    for (int i = 0; i < 4; i++) { vals[i] = xr[t + 256 * i]; s += vals[i]; }
    float mu = blockReduce256(s) * (1.f / NI);
    float s2 = 0.f;
#pragma unroll
    for (int i = 0; i < 4; i++) { float d = vals[i] - mu; s2 += d * d; }
    float var = blockReduce256(s2) * (1.f / NI);
    float rs = rsqrtf(var + EPS);
#pragma unroll
    for (int i = 0; i < 4; i++) {
        int c = t + 256 * i;
        g_xn[bi * NI + c] = (vals[i] - mu) * rs * w[c] + b[c];
    }
}

// ---------------- split-K GEMM partial, dual-job (select by blockIdx.z) ----------------
// Computes P_part = A[64,K] @ W[K,N] tile [64 x 64]. conv=1: W'[k][n]=Wc4[n*2048+k].w
struct GJob {
    const float* A; const float* W; float* P;
    int K, kc, N, conv;
};

__global__ __launch_bounds__(256) void gemm_k(GJob j0, GJob j1) {
    GJob j = blockIdx.z ? j1 : j0;
    __shared__ __align__(16) float As[64][36];
    __shared__ __align__(16) float Ws[32][68];
    int n0 = blockIdx.x * 64;
    int k0 = blockIdx.y * j.kc;
    int kend = min(k0 + j.kc, j.K);
    float* P = j.P + (size_t)blockIdx.y * 64 * j.N;
    int tx = threadIdx.x & 15, ty = threadIdx.x >> 4;
    float acc[4][4] = {};
    for (int kb = k0; kb < kend; kb += 32) {
        // A tile 64x32: float4 along k (coalesced), STS.128
#pragma unroll
        for (int r = 0; r < 2; r++) {
            int ee = threadIdx.x + r * 256;
            int k4 = ee & 7, m = ee >> 3;
            float4 v = *(const float4*)(j.A + (size_t)m * j.K + kb + 4 * k4);
            *(float4*)&As[m][4 * k4] = v;
        }
        if (!j.conv) {
            // W tile 32x64: float4 along n (coalesced), STS.128
#pragma unroll
            for (int r = 0; r < 2; r++) {
                int ee = threadIdx.x + r * 256;
                int n4 = ee & 15, k = ee >> 4;
                float4 v = *(const float4*)(j.W + (size_t)(kb + k) * j.N + n0 + 4 * n4);
                *(float4*)&Ws[k][4 * n4] = v;
            }
        } else {
            const float4* W4 = (const float4*)j.W;
#pragma unroll
            for (int r = 0; r < 8; r++) {
                int ee = threadIdx.x + r * 256;
                int k = ee & 31, n = ee >> 5;
                Ws[k][n] = W4[(size_t)(n0 + n) * 2048 + kb + k].w;
            }
        }
        __syncthreads();
#pragma unroll
        for (int kk = 0; kk < 32; kk++) {
            float4 w = *(const float4*)&Ws[kk][tx * 4];
            float a0 = As[ty * 4 + 0][kk];
            float a1 = As[ty * 4 + 1][kk];
            float a2 = As[ty * 4 + 2][kk];
            float a3 = As[ty * 4 + 3][kk];
            acc[0][0] += a0 * w.x; acc[0][1] += a0 * w.y; acc[0][2] += a0 * w.z; acc[0][3] += a0 * w.w;
            acc[1][0] += a1 * w.x; acc[1][1] += a1 * w.y; acc[1][2] += a1 * w.z; acc[1][3] += a1 * w.w;
            acc[2][0] += a2 * w.x; acc[2][1] += a2 * w.y; acc[2][2] += a2 * w.z; acc[2][3] += a2 * w.w;
            acc[3][0] += a3 * w.x; acc[3][1] += a3 * w.y; acc[3][2] += a3 * w.z; acc[3][3] += a3 * w.w;
        }
        __syncthreads();
    }
#pragma unroll
    for (int i = 0; i < 4; i++) {
        int m = ty * 4 + i;
        float4 v = make_float4(acc[i][0], acc[i][1], acc[i][2], acc[i][3]);
        *(float4*)(P + (size_t)m * j.N + n0 + tx * 4) = v;
    }
}

// ---------------- float4 split-K reduce + epilogue, dual-job ----------------
// mode: 0 bias, 1 silu, 2 sigmoid, 3 bias+residual
struct RJob {
    const float4* P; int np;
    const float4* bias; float4* C;
    int mode; const float4* R; int N4;
};

__global__ __launch_bounds__(256) void reduce_k(RJob r0, RJob r1) {
    RJob r = blockIdx.z ? r1 : r0;
    int idx = blockIdx.x * 256 + threadIdx.x;
    int total = 64 * r.N4;
    if (idx >= total) return;
    int n4 = idx % r.N4;
    float4 s = make_float4(0.f, 0.f, 0.f, 0.f);
#pragma unroll 4
    for (int p = 0; p < r.np; p++) {
        float4 v = r.P[(size_t)p * total + idx];
        s.x += v.x; s.y += v.y; s.z += v.z; s.w += v.w;
    }
    float4 b = r.bias[n4];
    s.x += b.x; s.y += b.y; s.z += b.z; s.w += b.w;
    if (r.mode == 1) {
        s.x = siluf_(s.x); s.y = siluf_(s.y); s.z = siluf_(s.z); s.w = siluf_(s.w);
    } else if (r.mode == 2) {
        s.x = sigmoidf_(s.x); s.y = sigmoidf_(s.y); s.z = sigmoidf_(s.z); s.w = sigmoidf_(s.w);
    } else if (r.mode == 3) {
        float4 rv = r.R[idx];
        s.x += rv.x; s.y += rv.y; s.z += rv.z; s.w += rv.w;
    }
    r.C[idx] = s;
}

// ---------------- block-diagonal q/k/v: tile 32(m) x 64(n), 128 thr ----------------
// grid: (4 ntiles, 2 mtiles, 24 = which*8+h). which: 0=q(xc), 1=k(xc,/16), 2=v(xl)
__global__ __launch_bounds__(128) void qkv_kernel(const float* __restrict__ Wq,
                                                  const float* __restrict__ Wk,
                                                  const float* __restrict__ Wv,
                                                  const float* __restrict__ bq,
                                                  const float* __restrict__ bk,
                                                  const float* __restrict__ bv) {
    int z = blockIdx.z;
    int which = z >> 3, h = z & 7;
    const float* A = (which == 2) ? g_xl : g_xc;
    const float* W; const float* bias; float* C; float scale = 1.f;
    if (which == 0) { W = Wq; bias = bq; C = g_q; }
    else if (which == 1) { W = Wk; bias = bk; C = g_k; scale = 0.0625f; }
    else { W = Wv; bias = bv; C = g_v; }
    W += (size_t)h * ND * ND;
    bias += h * ND;
    int n0 = blockIdx.x * 64;
    int m0 = blockIdx.y * 32;
    __shared__ __align__(16) float As[32][36];
    __shared__ __align__(16) float Ws[32][68];
    int tx = threadIdx.x & 15, ty = threadIdx.x >> 4;   // ty 0..7
    float acc[4][4] = {};
    for (int kb = 0; kb < ND; kb += 32) {
        // A tile 32x32
#pragma unroll
        for (int r = 0; r < 2; r++) {
            int ee = threadIdx.x + r * 128;
            int k4 = ee & 7, m = ee >> 3;
            float4 v = *(const float4*)(A + (size_t)(m0 + m) * NHID + h * ND + kb + 4 * k4);
            *(float4*)&As[m][4 * k4] = v;
        }
        // W tile 32x64
#pragma unroll
        for (int r = 0; r < 4; r++) {
            int ee = threadIdx.x + r * 128;
            int n4 = ee & 15, k = ee >> 4;
            float4 v = *(const float4*)(W + (size_t)(kb + k) * ND + n0 + 4 * n4);
            *(float4*)&Ws[k][4 * n4] = v;
        }
        __syncthreads();
#pragma unroll
        for (int kk = 0; kk < 32; kk++) {
            float4 w = *(const float4*)&Ws[kk][tx * 4];
            float a0 = As[ty * 4 + 0][kk];
            float a1 = As[ty * 4 + 1][kk];
            float a2 = As[ty * 4 + 2][kk];
            float a3 = As[ty * 4 + 3][kk];
            acc[0][0] += a0 * w.x; acc[0][1] += a0 * w.y; acc[0][2] += a0 * w.z; acc[0][3] += a0 * w.w;
            acc[1][0] += a1 * w.x; acc[1][1] += a1 * w.y; acc[1][2] += a1 * w.z; acc[1][3] += a1 * w.w;
            acc[2][0] += a2 * w.x; acc[2][1] += a2 * w.y; acc[2][2] += a2 * w.z; acc[2][3] += a2 * w.w;
            acc[3][0] += a3 * w.x; acc[3][1] += a3 * w.y; acc[3][2] += a3 * w.z; acc[3][3] += a3 * w.w;
        }
        __syncthreads();
    }
#pragma unroll
    for (int i = 0; i < 4; i++) {
        int m = m0 + ty * 4 + i;
        int n = n0 + tx * 4;
        float4 b4 = *(const float4*)(bias + n);
        float4 v = make_float4((acc[i][0] + b4.x) * scale, (acc[i][1] + b4.y) * scale,
                               (acc[i][2] + b4.z) * scale, (acc[i][3] + b4.w) * scale);
        *(float4*)(C + (size_t)m * NHID + h * ND + n) = v;
    }
}

// ---------------- i/f gate GEMVs + stabilized exp gating ----------------
__global__ __launch_bounds__(256) void gates_kernel(const float* __restrict__ Wi,
                                                    const float* __restrict__ bi,
                                                    const float* __restrict__ Wf,
                                                    const float* __restrict__ bf,
                                                    const float* __restrict__ m_prev,
                                                    float* __restrict__ m_out) {
    int b = blockIdx.x, t = threadIdx.x;
    float pi[8] = {}, pf[8] = {};
    for (int k = t; k < NHID; k += 256) {
        float xv = g_xc[b * NHID + k];
        const float4* wi4 = (const float4*)(Wi + k * 8);
        const float4* wf4 = (const float4*)(Wf + k * 8);
        float4 a0 = wi4[0], a1 = wi4[1], f0 = wf4[0], f1 = wf4[1];
        pi[0] += xv * a0.x; pi[1] += xv * a0.y; pi[2] += xv * a0.z; pi[3] += xv * a0.w;
        pi[4] += xv * a1.x; pi[5] += xv * a1.y; pi[6] += xv * a1.z; pi[7] += xv * a1.w;
        pf[0] += xv * f0.x; pf[1] += xv * f0.y; pf[2] += xv * f0.z; pf[3] += xv * f0.w;
        pf[4] += xv * f1.x; pf[5] += xv * f1.y; pf[6] += xv * f1.z; pf[7] += xv * f1.w;
    }
    __shared__ float s[256 * 16];
#pragma unroll
    for (int h = 0; h < 8; h++) { s[t * 16 + h] = pi[h]; s[t * 16 + 8 + h] = pf[h]; }
    __syncthreads();
    if (t < 16) {
        float a = 0.f;
        for (int r = 0; r < 256; r++) a += s[r * 16 + t];
        s[t] = a;
    }
    __syncthreads();
    if (t < 8) {
        float it = s[t] + bi[t];
        float ft = s[8 + t] + bf[t];
        float mp = m_prev[b * 8 + t];
        float m = fmaxf(ft + mp, it);
        m_out[b * 8 + t] = m;
        g_ig[b * 8 + t] = expf(it - m);
        g_fg[b * 8 + t] = expf(ft + mp - m);
    }
}

// ---------------- fused state update + readout + GroupNorm + gating ----------------
__global__ __launch_bounds__(256) void state_kernel(const float* __restrict__ c_prev,
                                                    const float* __restrict__ n_prev,
                                                    const float* __restrict__ gn_w,
                                                    const float* __restrict__ gn_b,
                                                    float* __restrict__ c_out,
                                                    float* __restrict__ n_out,
                                                    float* __restrict__ h_out) {
    int bh = blockIdx.x;
    int b = bh >> 3, h = bh & 7;
    int t = threadIdx.x;
    __shared__ __align__(16) float qs[256], ks[256], vs[256], hts[256];
    __shared__ float den_s;
    float fg = g_fg[bh], ig = g_ig[bh];
    int base = bh * ND;
    float qv = g_q[base + t], kv = g_k[base + t], vv = g_v[base + t];
    qs[t] = qv; ks[t] = kv; vs[t] = vv;
    float nt = fg * n_prev[base + t] + ig * kv;
    n_out[base + t] = nt;
    float den = blockReduce256(nt * qv);
    if (t == 0) den_s = fmaxf(den, 1.f);
    __syncthreads();
    den = den_s;
    int w = t >> 5, lane = t & 31;
    const float4* cp4 = (const float4*)(c_prev + (size_t)bh * ND * ND);
    float4* ct4 = (float4*)(c_out + (size_t)bh * ND * ND);
    const float4* qs4 = (const float4*)qs;
    const float4* ks4 = (const float4*)ks;
    // warp w owns rows [w*32, w*32+32), process 4 rows per iteration for ILP
    for (int d0 = w * 32; d0 < w * 32 + 32; d0 += 4) {
        float acc0 = 0.f, acc1 = 0.f, acc2 = 0.f, acc3 = 0.f;
        float vd0 = vs[d0 + 0] * ig, vd1 = vs[d0 + 1] * ig;
        float vd2 = vs[d0 + 2] * ig, vd3 = vs[d0 + 3] * ig;
#pragma unroll
        for (int p = 0; p < 2; p++) {
            int ci = lane + p * 32;
            float4 kk = ks4[ci];
            float4 qq = qs4[ci];
            float4 cp0 = cp4[(size_t)(d0 + 0) * 64 + ci];
            float4 cp1 = cp4[(size_t)(d0 + 1) * 64 + ci];
            float4 cp2 = cp4[(size_t)(d0 + 2) * 64 + ci];
            float4 cp3 = cp4[(size_t)(d0 + 3) * 64 + ci];
            float4 c0, c1, c2, c3;
            c0.x = fg * cp0.x + vd0 * kk.x; c0.y = fg * cp0.y + vd0 * kk.y;
            c0.z = fg * cp0.z + vd0 * kk.z; c0.w = fg * cp0.w + vd0 * kk.w;
            c1.x = fg * cp1.x + vd1 * kk.x; c1.y = fg * cp1.y + vd1 * kk.y;
            c1.z = fg * cp1.z + vd1 * kk.z; c1.w = fg * cp1.w + vd1 * kk.w;
            c2.x = fg * cp2.x + vd2 * kk.x; c2.y = fg * cp2.y + vd2 * kk.y;
            c2.z = fg * cp2.z + vd2 * kk.z; c2.w = fg * cp2.w + vd2 * kk.w;
            c3.x = fg * cp3.x + vd3 * kk.x; c3.y = fg * cp3.y + vd3 * kk.y;
            c3.z = fg * cp3.z + vd3 * kk.z; c3.w = fg * cp3.w + vd3 * kk.w;
            ct4[(size_t)(d0 + 0) * 64 + ci] = c0;
            ct4[(size_t)(d0 + 1) * 64 + ci] = c1;
            ct4[(size_t)(d0 + 2) * 64 + ci] = c2;
            ct4[(size_t)(d0 + 3) * 64 + ci] = c3;
            acc0 += c0.x * qq.x + c0.y * qq.y + c0.z * qq.z + c0.w * qq.w;
            acc1 += c1.x * qq.x + c1.y * qq.y + c1.z * qq.z + c1.w * qq.w;
            acc2 += c2.x * qq.x + c2.y * qq.y + c2.z * qq.z + c2.w * qq.w;
            acc3 += c3.x * qq.x + c3.y * qq.y + c3.z * qq.z + c3.w * qq.w;
        }
#pragma unroll
        for (int off = 16; off > 0; off >>= 1) {
            acc0 += __shfl_xor_sync(0xffffffffu, acc0, off);
            acc1 += __shfl_xor_sync(0xffffffffu, acc1, off);
            acc2 += __shfl_xor_sync(0xffffffffu, acc2, off);
            acc3 += __shfl_xor_sync(0xffffffffu, acc3, off);
        }
        if (lane == 0) {
            float h0 = g_o[base + d0 + 0] * acc0 / den;
            float h1 = g_o[base + d0 + 1] * acc1 / den;
            float h2 = g_o[base + d0 + 2] * acc2 / den;
            float h3 = g_o[base + d0 + 3] * acc3 / den;
            hts[d0 + 0] = h0; hts[d0 + 1] = h1; hts[d0 + 2] = h2; hts[d0 + 3] = h3;
            h_out[base + d0 + 0] = h0; h_out[base + d0 + 1] = h1;
            h_out[base + d0 + 2] = h2; h_out[base + d0 + 3] = h3;
        }
    }
    __syncthreads();
    // GroupNorm over D=256 + (gn + x_skip) * silu(xr)
    float hv = hts[t];
    float mu = blockReduce256(hv) * (1.f / ND);
    float dv = hv - mu;
    float var = blockReduce256(dv * dv) * (1.f / ND);
    float g = dv * rsqrtf(var + EPS);
    int hid = h * ND + t;
    float xrv = g_xr[b * NHID + hid];
    g_outpre[b * NHID + hid] =
        (g * gn_w[hid] + gn_b[hid] + g_xskip[b * NHID + hid]) * siluf_(xrv);
}

// ---------------- host launcher ----------------
extern "C" void kernel_launch(void* const* d_in, const int* in_sizes, int n_in,
                              void* d_out, int out_size) {
    (void)in_sizes; (void)n_in; (void)out_size;
    const float* x      = (const float*)d_in[0];
    const float* c_prev = (const float*)d_in[2];
    const float* n_prev = (const float*)d_in[3];
    const float* m_prev = (const float*)d_in[4];
    const float* ln_w   = (const float*)d_in[5];
    const float* ln_b   = (const float*)d_in[6];
    const float* W_ul   = (const float*)d_in[7];
    const float* b_ul   = (const float*)d_in[8];
    const float* W_ur   = (const float*)d_in[9];
    const float* b_ur   = (const float*)d_in[10];
    const float* W_conv = (const float*)d_in[11];
    const float* b_conv = (const float*)d_in[12];
    const float* W_skip = (const float*)d_in[13];
    const float* b_skip = (const float*)d_in[14];
    const float* W_q    = (const float*)d_in[15];
    const float* b_q    = (const float*)d_in[16];
    const float* W_k    = (const float*)d_in[17];
    const float* b_k    = (const float*)d_in[18];
    const float* W_v    = (const float*)d_in[19];
    const float* b_v    = (const float*)d_in[20];
    const float* W_i    = (const float*)d_in[21];
    const float* b_i    = (const float*)d_in[22];
    const float* W_f    = (const float*)d_in[23];
    const float* b_f    = (const float*)d_in[24];
    const float* W_o    = (const float*)d_in[25];
    const float* b_o    = (const float*)d_in[26];
    const float* W_down = (const float*)d_in[27];
    const float* b_down = (const float*)d_in[28];
    const float* gn_w   = (const float*)d_in[29];
    const float* gn_b   = (const float*)d_in[30];

    float* out = (float*)d_out;
    float* out_final = out;
    float* out_h = out + NB * NI;
    float* out_c = out_h + NB * NH * ND;
    float* out_n = out_c + (size_t)NB * NH * ND * ND;
    float* out_m = out_n + NB * NH * ND;

    void *p_xn, *p_xl, *p_xr, *p_xc, *p_xskip, *p_o, *p_outpre, *p_part;
    cudaGetSymbolAddress(&p_xn, g_xn);
    cudaGetSymbolAddress(&p_xl, g_xl);
    cudaGetSymbolAddress(&p_xr, g_xr);
    cudaGetSymbolAddress(&p_xc, g_xc);
    cudaGetSymbolAddress(&p_xskip, g_xskip);
    cudaGetSymbolAddress(&p_o, g_o);
    cudaGetSymbolAddress(&p_outpre, g_outpre);
    cudaGetSymbolAddress(&p_part, g_part);
    float* xn = (float*)p_xn;
    float* xl = (float*)p_xl;
    float* xr = (float*)p_xr;
    float* xc = (float*)p_xc;
    float* xskip = (float*)p_xskip;
    float* o = (float*)p_o;
    float* outpre = (float*)p_outpre;
    float* part = (float*)p_part;

    const int SLOT = NB * NHID;   // 131072 floats per partial slot

    // 1. LayerNorm
    ln_kernel<<<NB, 256>>>(x, ln_w, ln_b);

    // 2. xl = xn@W_ul (slots 0..3), xr = xn@W_ur (slots 4..7): K=1024, 4-way split
    {
        GJob a{xn, W_ul, part, NI, 256, NHID, 0};
        GJob b2{xn, W_ur, part + (size_t)4 * SLOT, NI, 256, NHID, 0};
        gemm_k<<<dim3(32, 4, 2), 256>>>(a, b2);
        RJob ra{(const float4*)part, 4, (const float4*)b_ul, (float4*)xl, 0, nullptr, NHID / 4};
        RJob rb{(const float4*)(part + (size_t)4 * SLOT), 4, (const float4*)b_ur, (float4*)xr, 0, nullptr, NHID / 4};
        reduce_k<<<dim3(128, 1, 2), 256>>>(ra, rb);
    }

    // 3. conv (slots 0..7) + o-pre (slots 8..15): both from xl, K=2048, 8-way split
    {
        GJob a{xl, W_conv, part, NHID, 256, NHID, 1};
        GJob b2{xl, W_o, part + (size_t)8 * SLOT, NHID, 256, NHID, 0};
        gemm_k<<<dim3(32, 8, 2), 256>>>(a, b2);
        RJob ra{(const float4*)part, 8, (const float4*)b_conv, (float4*)xc, 1, nullptr, NHID / 4};       // silu
        RJob rb{(const float4*)(part + (size_t)8 * SLOT), 8, (const float4*)b_o, (float4*)o, 2, nullptr, NHID / 4};  // sigmoid
        reduce_k<<<dim3(128, 1, 2), 256>>>(ra, rb);
    }

    // 4. skip GEMM (from xc) + qkv + gates
    {
        GJob a{xc, W_skip, part, NHID, 256, NHID, 0};
        gemm_k<<<dim3(32, 8, 1), 256>>>(a, a);
        qkv_kernel<<<dim3(4, 2, 24), 128>>>(W_q, W_k, W_v, b_q, b_k, b_v);
        gates_kernel<<<NB, 256>>>(W_i, b_i, W_f, b_f, m_prev, out_m);
        RJob ra{(const float4*)part, 8, (const float4*)b_skip, (float4*)xskip, 0, nullptr, NHID / 4};
        reduce_k<<<dim3(128, 1, 1), 256>>>(ra, ra);
    }

    // 5. fused state update / readout / groupnorm / gating
    state_kernel<<<NB * NH, 256>>>(c_prev, n_prev, gn_w, gn_b, out_c, out_n, out_h);

    // 6. final = outpre @ W_down + b_down + x : K=2048, 16-way split, N=1024
    {
        GJob a{outpre, W_down, part, NHID, 128, NI, 0};
        gemm_k<<<dim3(16, 16, 1), 256>>>(a, a);
        RJob ra{(const float4*)part, 16, (const float4*)b_down, (float4*)out_final, 3, (const float4*)x, NI / 4};
        reduce_k<<<dim3(64, 1, 1), 256>>>(ra, ra);
    }
}

// round 3
// speedup vs baseline: 1.6477x; 1.1895x over previous
#include <cuda_runtime.h>
#include <cuda_bf16.h>
#include <math.h>

#define NB   64
#define NI   1024
#define NHID 2048
#define NH   8
#define ND   256
#define EPS  1e-5f

// ---------------- device scratch ----------------
__device__ float g_xn[NB * NI];
__device__ float g_xl[NB * NHID];
__device__ float g_xr[NB * NHID];
__device__ float g_xc[NB * NHID];
__device__ float g_xskip[NB * NHID];
__device__ float g_o[NB * NHID];
__device__ float g_q[NB * NHID];
__device__ float g_k[NB * NHID];
__device__ float g_v[NB * NHID];
__device__ float g_outpre[NB * NHID];
__device__ float g_ig[NB * NH];
__device__ float g_fg[NB * NH];
__device__ float g_part[16 * NB * NHID];   // 16 split-K partial slots (8MB)

// ---------------- helpers ----------------
__device__ __forceinline__ float blockReduce256(float v) {
    __shared__ float red[256];
    int t = threadIdx.x;
    red[t] = v;
    __syncthreads();
#pragma unroll
    for (int s = 128; s > 0; s >>= 1) {
        if (t < s) red[t] += red[t + s];
        __syncthreads();
    }
    float r = red[0];
    __syncthreads();
    return r;
}
__device__ __forceinline__ float sigmoidf_(float x) { return 1.f / (1.f + expf(-x)); }
__device__ __forceinline__ float siluf_(float x) { return x / (1.f + expf(-x)); }

// ---------------- LayerNorm ----------------
__global__ __launch_bounds__(256) void ln_kernel(const float* __restrict__ x,
                                                 const float* __restrict__ w,
                                                 const float* __restrict__ b) {
    int bi = blockIdx.x, t = threadIdx.x;
    const float* xr = x + bi * NI;
    float vals[4];
    float s = 0.f;
#pragma unroll
    for (int i = 0; i < 4; i++) { vals[i] = xr[t + 256 * i]; s += vals[i]; }
    float mu = blockReduce256(s) * (1.f / NI);
    float s2 = 0.f;
#pragma unroll
    for (int i = 0; i < 4; i++) { float d = vals[i] - mu; s2 += d * d; }
    float var = blockReduce256(s2) * (1.f / NI);
    float rs = rsqrtf(var + EPS);
#pragma unroll
    for (int i = 0; i < 4; i++) {
        int c = t + 256 * i;
        g_xn[bi * NI + c] = (vals[i] - mu) * rs * w[c] + b[c];
    }
}

// ---------------- split-K GEMM: 64(M) x 128(N) tile, software pipelined ----------------
// conv=1: W element (k,n) lives at Wc[((n)*2048 + k)*4 + 3] (scalar loads)
struct GJob {
    const float* A; const float* W; float* P;
    int K, kc, N, conv;
};

__global__ __launch_bounds__(256, 2) void gemm_k2(GJob j0, GJob j1) {
    GJob j = blockIdx.z ? j1 : j0;
    __shared__ __align__(16) float As[32][72];     // k-major A tile
    __shared__ __align__(16) float Ws[32][132];    // k-major W tile
    const int tid = threadIdx.x;
    const int n0 = blockIdx.x * 128;
    const int k0 = blockIdx.y * j.kc;
    const int nst = j.kc >> 5;
    float* P = j.P + (size_t)blockIdx.y * 64 * j.N;
    const int tx = tid & 31, ty = tid >> 5;

    // A staging map: thread -> (m = tid>>2, k-offset = (tid&3)*8), loads 2 float4
    const int am = tid >> 2;
    const int ak = (tid & 3) * 8;
    // W staging maps
    float aR0x, aR0y, aR0z, aR0w, aR1x, aR1y, aR1z, aR1w;
    float wst[16];

    float acc[8][4] = {};

    // ---- prologue: load stage 0 ----
    {
        int kb = k0;
        const float* Ap = j.A + (size_t)am * j.K + kb + ak;
        float4 a0 = *(const float4*)(Ap);
        float4 a1 = *(const float4*)(Ap + 4);
        aR0x = a0.x; aR0y = a0.y; aR0z = a0.z; aR0w = a0.w;
        aR1x = a1.x; aR1y = a1.y; aR1z = a1.z; aR1w = a1.w;
        if (!j.conv) {
#pragma unroll
            for (int r = 0; r < 4; r++) {
                int e = tid + r * 256;
                int wk = e >> 5, wn4 = e & 31;
                float4 v = *(const float4*)(j.W + (size_t)(kb + wk) * j.N + n0 + wn4 * 4);
                wst[r * 4 + 0] = v.x; wst[r * 4 + 1] = v.y; wst[r * 4 + 2] = v.z; wst[r * 4 + 3] = v.w;
            }
        } else {
#pragma unroll
            for (int r = 0; r < 16; r++) {
                int e = tid + r * 256;
                int ck = e & 31, cn = e >> 5;
                wst[r] = j.W[((size_t)(n0 + cn) * 2048 + (kb + ck)) * 4 + 3];
            }
        }
    }
    // store stage 0
    {
        As[ak + 0][am] = aR0x; As[ak + 1][am] = aR0y; As[ak + 2][am] = aR0z; As[ak + 3][am] = aR0w;
        As[ak + 4][am] = aR1x; As[ak + 5][am] = aR1y; As[ak + 6][am] = aR1z; As[ak + 7][am] = aR1w;
        if (!j.conv) {
#pragma unroll
            for (int r = 0; r < 4; r++) {
                int e = tid + r * 256;
                int wk = e >> 5, wn4 = e & 31;
                float4 v = make_float4(wst[r * 4 + 0], wst[r * 4 + 1], wst[r * 4 + 2], wst[r * 4 + 3]);
                *(float4*)&Ws[wk][wn4 * 4] = v;
            }
        } else {
#pragma unroll
            for (int r = 0; r < 16; r++) {
                int e = tid + r * 256;
                int ck = e & 31, cn = e >> 5;
                Ws[ck][cn] = wst[r];
            }
        }
    }
    __syncthreads();

    for (int s = 0; s < nst; s++) {
        // ---- prefetch next stage into registers ----
        if (s + 1 < nst) {
            int kb = k0 + (s + 1) * 32;
            const float* Ap = j.A + (size_t)am * j.K + kb + ak;
            float4 a0 = *(const float4*)(Ap);
            float4 a1 = *(const float4*)(Ap + 4);
            aR0x = a0.x; aR0y = a0.y; aR0z = a0.z; aR0w = a0.w;
            aR1x = a1.x; aR1y = a1.y; aR1z = a1.z; aR1w = a1.w;
            if (!j.conv) {
#pragma unroll
                for (int r = 0; r < 4; r++) {
                    int e = tid + r * 256;
                    int wk = e >> 5, wn4 = e & 31;
                    float4 v = *(const float4*)(j.W + (size_t)(kb + wk) * j.N + n0 + wn4 * 4);
                    wst[r * 4 + 0] = v.x; wst[r * 4 + 1] = v.y; wst[r * 4 + 2] = v.z; wst[r * 4 + 3] = v.w;
                }
            } else {
#pragma unroll
                for (int r = 0; r < 16; r++) {
                    int e = tid + r * 256;
                    int ck = e & 31, cn = e >> 5;
                    wst[r] = j.W[((size_t)(n0 + cn) * 2048 + (kb + ck)) * 4 + 3];
                }
            }
        }
        // ---- compute on current smem stage ----
#pragma unroll
        for (int kk = 0; kk < 32; kk++) {
            float4 a0 = *(const float4*)&As[kk][ty * 8];
            float4 a1 = *(const float4*)&As[kk][ty * 8 + 4];
            float4 w = *(const float4*)&Ws[kk][tx * 4];
            float am8[8] = {a0.x, a0.y, a0.z, a0.w, a1.x, a1.y, a1.z, a1.w};
#pragma unroll
            for (int i = 0; i < 8; i++) {
                acc[i][0] += am8[i] * w.x;
                acc[i][1] += am8[i] * w.y;
                acc[i][2] += am8[i] * w.z;
                acc[i][3] += am8[i] * w.w;
            }
        }
        __syncthreads();
        // ---- store next stage ----
        if (s + 1 < nst) {
            As[ak + 0][am] = aR0x; As[ak + 1][am] = aR0y; As[ak + 2][am] = aR0z; As[ak + 3][am] = aR0w;
            As[ak + 4][am] = aR1x; As[ak + 5][am] = aR1y; As[ak + 6][am] = aR1z; As[ak + 7][am] = aR1w;
            if (!j.conv) {
#pragma unroll
                for (int r = 0; r < 4; r++) {
                    int e = tid + r * 256;
                    int wk = e >> 5, wn4 = e & 31;
                    float4 v = make_float4(wst[r * 4 + 0], wst[r * 4 + 1], wst[r * 4 + 2], wst[r * 4 + 3]);
                    *(float4*)&Ws[wk][wn4 * 4] = v;
                }
            } else {
#pragma unroll
                for (int r = 0; r < 16; r++) {
                    int e = tid + r * 256;
                    int ck = e & 31, cn = e >> 5;
                    Ws[ck][cn] = wst[r];
                }
            }
            __syncthreads();
        }
    }

    // ---- write partials ----
#pragma unroll
    for (int i = 0; i < 8; i++) {
        int m = ty * 8 + i;
        float4 v = make_float4(acc[i][0], acc[i][1], acc[i][2], acc[i][3]);
        *(float4*)(P + (size_t)m * j.N + n0 + tx * 4) = v;
    }
}

// ---------------- float4 split-K reduce + epilogue, dual-job ----------------
// mode: 0 bias, 1 silu, 2 sigmoid, 3 bias+residual
struct RJob {
    const float4* P; int np;
    const float4* bias; float4* C;
    int mode; const float4* R; int N4;
};

__global__ __launch_bounds__(256) void reduce_k(RJob r0, RJob r1) {
    RJob r = blockIdx.z ? r1 : r0;
    int idx = blockIdx.x * 256 + threadIdx.x;
    int total = 64 * r.N4;
    if (idx >= total) return;
    int n4 = idx % r.N4;
    float4 s = make_float4(0.f, 0.f, 0.f, 0.f);
#pragma unroll 4
    for (int p = 0; p < r.np; p++) {
        float4 v = r.P[(size_t)p * total + idx];
        s.x += v.x; s.y += v.y; s.z += v.z; s.w += v.w;
    }
    float4 b = r.bias[n4];
    s.x += b.x; s.y += b.y; s.z += b.z; s.w += b.w;
    if (r.mode == 1) {
        s.x = siluf_(s.x); s.y = siluf_(s.y); s.z = siluf_(s.z); s.w = siluf_(s.w);
    } else if (r.mode == 2) {
        s.x = sigmoidf_(s.x); s.y = sigmoidf_(s.y); s.z = sigmoidf_(s.z); s.w = sigmoidf_(s.w);
    } else if (r.mode == 3) {
        float4 rv = r.R[idx];
        s.x += rv.x; s.y += rv.y; s.z += rv.z; s.w += rv.w;
    }
    r.C[idx] = s;
}

// ---------------- block-diagonal q/k/v: tile 32(m) x 64(n), 128 thr ----------------
__global__ __launch_bounds__(128) void qkv_kernel(const float* __restrict__ Wq,
                                                  const float* __restrict__ Wk,
                                                  const float* __restrict__ Wv,
                                                  const float* __restrict__ bq,
                                                  const float* __restrict__ bk,
                                                  const float* __restrict__ bv) {
    int z = blockIdx.z;
    int which = z >> 3, h = z & 7;
    const float* A = (which == 2) ? g_xl : g_xc;
    const float* W; const float* bias; float* C; float scale = 1.f;
    if (which == 0) { W = Wq; bias = bq; C = g_q; }
    else if (which == 1) { W = Wk; bias = bk; C = g_k; scale = 0.0625f; }
    else { W = Wv; bias = bv; C = g_v; }
    W += (size_t)h * ND * ND;
    bias += h * ND;
    int n0 = blockIdx.x * 64;
    int m0 = blockIdx.y * 32;
    __shared__ __align__(16) float As[32][36];
    __shared__ __align__(16) float Ws[32][68];
    int tx = threadIdx.x & 15, ty = threadIdx.x >> 4;
    float acc[4][4] = {};
    for (int kb = 0; kb < ND; kb += 32) {
#pragma unroll
        for (int r = 0; r < 2; r++) {
            int ee = threadIdx.x + r * 128;
            int k4 = ee & 7, m = ee >> 3;
            float4 v = *(const float4*)(A + (size_t)(m0 + m) * NHID + h * ND + kb + 4 * k4);
            *(float4*)&As[m][4 * k4] = v;
        }
#pragma unroll
        for (int r = 0; r < 4; r++) {
            int ee = threadIdx.x + r * 128;
            int n4 = ee & 15, k = ee >> 4;
            float4 v = *(const float4*)(W + (size_t)(kb + k) * ND + n0 + 4 * n4);
            *(float4*)&Ws[k][4 * n4] = v;
        }
        __syncthreads();
#pragma unroll
        for (int kk = 0; kk < 32; kk++) {
            float4 w = *(const float4*)&Ws[kk][tx * 4];
            float a0 = As[ty * 4 + 0][kk];
            float a1 = As[ty * 4 + 1][kk];
            float a2 = As[ty * 4 + 2][kk];
            float a3 = As[ty * 4 + 3][kk];
            acc[0][0] += a0 * w.x; acc[0][1] += a0 * w.y; acc[0][2] += a0 * w.z; acc[0][3] += a0 * w.w;
            acc[1][0] += a1 * w.x; acc[1][1] += a1 * w.y; acc[1][2] += a1 * w.z; acc[1][3] += a1 * w.w;
            acc[2][0] += a2 * w.x; acc[2][1] += a2 * w.y; acc[2][2] += a2 * w.z; acc[2][3] += a2 * w.w;
            acc[3][0] += a3 * w.x; acc[3][1] += a3 * w.y; acc[3][2] += a3 * w.z; acc[3][3] += a3 * w.w;
        }
        __syncthreads();
    }
#pragma unroll
    for (int i = 0; i < 4; i++) {
        int m = m0 + ty * 4 + i;
        int n = n0 + tx * 4;
        float4 b4 = *(const float4*)(bias + n);
        float4 v = make_float4((acc[i][0] + b4.x) * scale, (acc[i][1] + b4.y) * scale,
                               (acc[i][2] + b4.z) * scale, (acc[i][3] + b4.w) * scale);
        *(float4*)(C + (size_t)m * NHID + h * ND + n) = v;
    }
}

// ---------------- i/f gate GEMVs + stabilized exp gating ----------------
__global__ __launch_bounds__(256) void gates_kernel(const float* __restrict__ Wi,
                                                    const float* __restrict__ bi,
                                                    const float* __restrict__ Wf,
                                                    const float* __restrict__ bf,
                                                    const float* __restrict__ m_prev,
                                                    float* __restrict__ m_out) {
    int b = blockIdx.x, t = threadIdx.x;
    float pi[8] = {}, pf[8] = {};
    for (int k = t; k < NHID; k += 256) {
        float xv = g_xc[b * NHID + k];
        const float4* wi4 = (const float4*)(Wi + k * 8);
        const float4* wf4 = (const float4*)(Wf + k * 8);
        float4 a0 = wi4[0], a1 = wi4[1], f0 = wf4[0], f1 = wf4[1];
        pi[0] += xv * a0.x; pi[1] += xv * a0.y; pi[2] += xv * a0.z; pi[3] += xv * a0.w;
        pi[4] += xv * a1.x; pi[5] += xv * a1.y; pi[6] += xv * a1.z; pi[7] += xv * a1.w;
        pf[0] += xv * f0.x; pf[1] += xv * f0.y; pf[2] += xv * f0.z; pf[3] += xv * f0.w;
        pf[4] += xv * f1.x; pf[5] += xv * f1.y; pf[6] += xv * f1.z; pf[7] += xv * f1.w;
    }
    __shared__ float s[256 * 16];
#pragma unroll
    for (int h = 0; h < 8; h++) { s[t * 16 + h] = pi[h]; s[t * 16 + 8 + h] = pf[h]; }
    __syncthreads();
    if (t < 16) {
        float a = 0.f;
        for (int r = 0; r < 256; r++) a += s[r * 16 + t];
        s[t] = a;
    }
    __syncthreads();
    if (t < 8) {
        float it = s[t] + bi[t];
        float ft = s[8 + t] + bf[t];
        float mp = m_prev[b * 8 + t];
        float m = fmaxf(ft + mp, it);
        m_out[b * 8 + t] = m;
        g_ig[b * 8 + t] = expf(it - m);
        g_fg[b * 8 + t] = expf(ft + mp - m);
    }
}

// ---------------- fused state update + readout + GroupNorm + gating ----------------
__global__ __launch_bounds__(256) void state_kernel(const float* __restrict__ c_prev,
                                                    const float* __restrict__ n_prev,
                                                    const float* __restrict__ gn_w,
                                                    const float* __restrict__ gn_b,
                                                    float* __restrict__ c_out,
                                                    float* __restrict__ n_out,
                                                    float* __restrict__ h_out) {
    int bh = blockIdx.x;
    int b = bh >> 3, h = bh & 7;
    int t = threadIdx.x;
    __shared__ __align__(16) float qs[256], ks[256], vs[256], hts[256];
    __shared__ float den_s;
    float fg = g_fg[bh], ig = g_ig[bh];
    int base = bh * ND;
    float qv = g_q[base + t], kv = g_k[base + t], vv = g_v[base + t];
    qs[t] = qv; ks[t] = kv; vs[t] = vv;
    float nt = fg * n_prev[base + t] + ig * kv;
    n_out[base + t] = nt;
    float den = blockReduce256(nt * qv);
    if (t == 0) den_s = fmaxf(den, 1.f);
    __syncthreads();
    den = den_s;
    int w = t >> 5, lane = t & 31;
    const float4* cp4 = (const float4*)(c_prev + (size_t)bh * ND * ND);
    float4* ct4 = (float4*)(c_out + (size_t)bh * ND * ND);
    const float4* qs4 = (const float4*)qs;
    const float4* ks4 = (const float4*)ks;
    for (int d0 = w * 32; d0 < w * 32 + 32; d0 += 4) {
        float acc0 = 0.f, acc1 = 0.f, acc2 = 0.f, acc3 = 0.f;
        float vd0 = vs[d0 + 0] * ig, vd1 = vs[d0 + 1] * ig;
        float vd2 = vs[d0 + 2] * ig, vd3 = vs[d0 + 3] * ig;
#pragma unroll
        for (int p = 0; p < 2; p++) {
            int ci = lane + p * 32;
            float4 kk = ks4[ci];
            float4 qq = qs4[ci];
            float4 cp0 = cp4[(size_t)(d0 + 0) * 64 + ci];
            float4 cp1 = cp4[(size_t)(d0 + 1) * 64 + ci];
            float4 cp2 = cp4[(size_t)(d0 + 2) * 64 + ci];
            float4 cp3 = cp4[(size_t)(d0 + 3) * 64 + ci];
            float4 c0, c1, c2, c3;
            c0.x = fg * cp0.x + vd0 * kk.x; c0.y = fg * cp0.y + vd0 * kk.y;
            c0.z = fg * cp0.z + vd0 * kk.z; c0.w = fg * cp0.w + vd0 * kk.w;
            c1.x = fg * cp1.x + vd1 * kk.x; c1.y = fg * cp1.y + vd1 * kk.y;
            c1.z = fg * cp1.z + vd1 * kk.z; c1.w = fg * cp1.w + vd1 * kk.w;
            c2.x = fg * cp2.x + vd2 * kk.x; c2.y = fg * cp2.y + vd2 * kk.y;
            c2.z = fg * cp2.z + vd2 * kk.z; c2.w = fg * cp2.w + vd2 * kk.w;
            c3.x = fg * cp3.x + vd3 * kk.x; c3.y = fg * cp3.y + vd3 * kk.y;
            c3.z = fg * cp3.z + vd3 * kk.z; c3.w = fg * cp3.w + vd3 * kk.w;
            ct4[(size_t)(d0 + 0) * 64 + ci] = c0;
            ct4[(size_t)(d0 + 1) * 64 + ci] = c1;
            ct4[(size_t)(d0 + 2) * 64 + ci] = c2;
            ct4[(size_t)(d0 + 3) * 64 + ci] = c3;
            acc0 += c0.x * qq.x + c0.y * qq.y + c0.z * qq.z + c0.w * qq.w;
            acc1 += c1.x * qq.x + c1.y * qq.y + c1.z * qq.z + c1.w * qq.w;
            acc2 += c2.x * qq.x + c2.y * qq.y + c2.z * qq.z + c2.w * qq.w;
            acc3 += c3.x * qq.x + c3.y * qq.y + c3.z * qq.z + c3.w * qq.w;
        }
#pragma unroll
        for (int off = 16; off > 0; off >>= 1) {
            acc0 += __shfl_xor_sync(0xffffffffu, acc0, off);
            acc1 += __shfl_xor_sync(0xffffffffu, acc1, off);
            acc2 += __shfl_xor_sync(0xffffffffu, acc2, off);
            acc3 += __shfl_xor_sync(0xffffffffu, acc3, off);
        }
        if (lane == 0) {
            float h0 = g_o[base + d0 + 0] * acc0 / den;
            float h1 = g_o[base + d0 + 1] * acc1 / den;
            float h2 = g_o[base + d0 + 2] * acc2 / den;
            float h3 = g_o[base + d0 + 3] * acc3 / den;
            hts[d0 + 0] = h0; hts[d0 + 1] = h1; hts[d0 + 2] = h2; hts[d0 + 3] = h3;
            h_out[base + d0 + 0] = h0; h_out[base + d0 + 1] = h1;
            h_out[base + d0 + 2] = h2; h_out[base + d0 + 3] = h3;
        }
    }
    __syncthreads();
    float hv = hts[t];
    float mu = blockReduce256(hv) * (1.f / ND);
    float dv = hv - mu;
    float var = blockReduce256(dv * dv) * (1.f / ND);
    float g = dv * rsqrtf(var + EPS);
    int hid = h * ND + t;
    float xrv = g_xr[b * NHID + hid];
    g_outpre[b * NHID + hid] =
        (g * gn_w[hid] + gn_b[hid] + g_xskip[b * NHID + hid]) * siluf_(xrv);
}

// ---------------- host launcher ----------------
extern "C" void kernel_launch(void* const* d_in, const int* in_sizes, int n_in,
                              void* d_out, int out_size) {
    (void)in_sizes; (void)n_in; (void)out_size;
    const float* x      = (const float*)d_in[0];
    const float* c_prev = (const float*)d_in[2];
    const float* n_prev = (const float*)d_in[3];
    const float* m_prev = (const float*)d_in[4];
    const float* ln_w   = (const float*)d_in[5];
    const float* ln_b   = (const float*)d_in[6];
    const float* W_ul   = (const float*)d_in[7];
    const float* b_ul   = (const float*)d_in[8];
    const float* W_ur   = (const float*)d_in[9];
    const float* b_ur   = (const float*)d_in[10];
    const float* W_conv = (const float*)d_in[11];
    const float* b_conv = (const float*)d_in[12];
    const float* W_skip = (const float*)d_in[13];
    const float* b_skip = (const float*)d_in[14];
    const float* W_q    = (const float*)d_in[15];
    const float* b_q    = (const float*)d_in[16];
    const float* W_k    = (const float*)d_in[17];
    const float* b_k    = (const float*)d_in[18];
    const float* W_v    = (const float*)d_in[19];
    const float* b_v    = (const float*)d_in[20];
    const float* W_i    = (const float*)d_in[21];
    const float* b_i    = (const float*)d_in[22];
    const float* W_f    = (const float*)d_in[23];
    const float* b_f    = (const float*)d_in[24];
    const float* W_o    = (const float*)d_in[25];
    const float* b_o    = (const float*)d_in[26];
    const float* W_down = (const float*)d_in[27];
    const float* b_down = (const float*)d_in[28];
    const float* gn_w   = (const float*)d_in[29];
    const float* gn_b   = (const float*)d_in[30];

    float* out = (float*)d_out;
    float* out_final = out;
    float* out_h = out + NB * NI;
    float* out_c = out_h + NB * NH * ND;
    float* out_n = out_c + (size_t)NB * NH * ND * ND;
    float* out_m = out_n + NB * NH * ND;

    void *p_xn, *p_xl, *p_xr, *p_xc, *p_xskip, *p_o, *p_outpre, *p_part;
    cudaGetSymbolAddress(&p_xn, g_xn);
    cudaGetSymbolAddress(&p_xl, g_xl);
    cudaGetSymbolAddress(&p_xr, g_xr);
    cudaGetSymbolAddress(&p_xc, g_xc);
    cudaGetSymbolAddress(&p_xskip, g_xskip);
    cudaGetSymbolAddress(&p_o, g_o);
    cudaGetSymbolAddress(&p_outpre, g_outpre);
    cudaGetSymbolAddress(&p_part, g_part);
    float* xn = (float*)p_xn;
    float* xl = (float*)p_xl;
    float* xr = (float*)p_xr;
    float* xc = (float*)p_xc;
    float* xskip = (float*)p_xskip;
    float* o = (float*)p_o;
    float* outpre = (float*)p_outpre;
    float* part = (float*)p_part;

    const int SLOT = NB * NHID;   // 131072 floats per partial slot

    // 1. LayerNorm
    ln_kernel<<<NB, 256>>>(x, ln_w, ln_b);

    // 2. xl = xn@W_ul (slots 0..7), xr = xn@W_ur (slots 8..15): K=1024, 8-way split
    {
        GJob a{xn, W_ul, part, NI, 128, NHID, 0};
        GJob b2{xn, W_ur, part + (size_t)8 * SLOT, NI, 128, NHID, 0};
        gemm_k2<<<dim3(16, 8, 2), 256>>>(a, b2);
        RJob ra{(const float4*)part, 8, (const float4*)b_ul, (float4*)xl, 0, nullptr, NHID / 4};
        RJob rb{(const float4*)(part + (size_t)8 * SLOT), 8, (const float4*)b_ur, (float4*)xr, 0, nullptr, NHID / 4};
        reduce_k<<<dim3(128, 1, 2), 256>>>(ra, rb);
    }

    // 3. conv (slots 0..7) + o-pre (slots 8..15): both from xl, K=2048, 8-way split
    {
        GJob a{xl, W_conv, part, NHID, 256, NHID, 1};
        GJob b2{xl, W_o, part + (size_t)8 * SLOT, NHID, 256, NHID, 0};
        gemm_k2<<<dim3(16, 8, 2), 256>>>(a, b2);
        RJob ra{(const float4*)part, 8, (const float4*)b_conv, (float4*)xc, 1, nullptr, NHID / 4};
        RJob rb{(const float4*)(part + (size_t)8 * SLOT), 8, (const float4*)b_o, (float4*)o, 2, nullptr, NHID / 4};
        reduce_k<<<dim3(128, 1, 2), 256>>>(ra, rb);
    }

    // 4. skip GEMM (from xc, 16-way split) + qkv + gates
    {
        GJob a{xc, W_skip, part, NHID, 128, NHID, 0};
        gemm_k2<<<dim3(16, 16, 1), 256>>>(a, a);
        qkv_kernel<<<dim3(4, 2, 24), 128>>>(W_q, W_k, W_v, b_q, b_k, b_v);
        gates_kernel<<<NB, 256>>>(W_i, b_i, W_f, b_f, m_prev, out_m);
        RJob ra{(const float4*)part, 16, (const float4*)b_skip, (float4*)xskip, 0, nullptr, NHID / 4};
        reduce_k<<<dim3(128, 1, 1), 256>>>(ra, ra);
    }

    // 5. fused state update / readout / groupnorm / gating
    state_kernel<<<NB * NH, 256>>>(c_prev, n_prev, gn_w, gn_b, out_c, out_n, out_h);

    // 6. final = outpre @ W_down + b_down + x : K=2048, 32-way split, N=1024
    {
        GJob a{outpre, W_down, part, NHID, 64, NI, 0};
        gemm_k2<<<dim3(8, 32, 1), 256>>>(a, a);
        RJob ra{(const float4*)part, 32, (const float4*)b_down, (float4*)out_final, 3, (const float4*)x, NI / 4};
        reduce_k<<<dim3(64, 1, 1), 256>>>(ra, ra);
    }
}

// round 4
// speedup vs baseline: 1.7653x; 1.0714x over previous
#include <cuda_runtime.h>
#include <cuda_bf16.h>
#include <math.h>
#include <stdint.h>

#define NB   64
#define NI   1024
#define NHID 2048
#define NH   8
#define ND   256
#define EPS  1e-5f

// ---------------- device scratch ----------------
__device__ float g_xn[NB * NI];
__device__ float g_xl[NB * NHID];
__device__ float g_xr[NB * NHID];
__device__ float g_xc[NB * NHID];
__device__ float g_xskip[NB * NHID];
__device__ float g_o[NB * NHID];
__device__ float g_q[NB * NHID];
__device__ float g_k[NB * NHID];
__device__ float g_v[NB * NHID];
__device__ float g_outpre[NB * NHID];
__device__ float g_ig[NB * NH];
__device__ float g_fg[NB * NH];
__device__ float g_part[16 * NB * NHID];   // 16 split-K partial slots (8MB)

// ---------------- helpers ----------------
__device__ __forceinline__ float blockReduce256(float v) {
    __shared__ float red[256];
    int t = threadIdx.x;
    red[t] = v;
    __syncthreads();
#pragma unroll
    for (int s = 128; s > 0; s >>= 1) {
        if (t < s) red[t] += red[t + s];
        __syncthreads();
    }
    float r = red[0];
    __syncthreads();
    return r;
}
__device__ __forceinline__ float sigmoidf_(float x) { return 1.f / (1.f + expf(-x)); }
__device__ __forceinline__ float siluf_(float x) { return x / (1.f + expf(-x)); }

// split a float pair into bf16x2 hi and lo words (low half = first element)
__device__ __forceinline__ void pack_hl(float x, float y, uint32_t& hi, uint32_t& lo) {
    __nv_bfloat162 h = __float22bfloat162_rn(make_float2(x, y));
    float2 hf = __bfloat1622float2(h);
    __nv_bfloat162 l = __float22bfloat162_rn(make_float2(x - hf.x, y - hf.y));
    hi = *(uint32_t*)&h;
    lo = *(uint32_t*)&l;
}

__device__ __forceinline__ void mma_bf16(float* acc, uint32_t a0, uint32_t a1,
                                         uint32_t a2, uint32_t a3,
                                         uint32_t b0, uint32_t b1) {
    asm volatile(
        "mma.sync.aligned.m16n8k16.row.col.f32.bf16.bf16.f32 "
        "{%0,%1,%2,%3}, {%4,%5,%6,%7}, {%8,%9}, {%0,%1,%2,%3};"
        : "+f"(acc[0]), "+f"(acc[1]), "+f"(acc[2]), "+f"(acc[3])
        : "r"(a0), "r"(a1), "r"(a2), "r"(a3), "r"(b0), "r"(b1));
}

// ---------------- LayerNorm ----------------
__global__ __launch_bounds__(256) void ln_kernel(const float* __restrict__ x,
                                                 const float* __restrict__ w,
                                                 const float* __restrict__ b) {
    int bi = blockIdx.x, t = threadIdx.x;
    const float* xr = x + bi * NI;
    float vals[4];
    float s = 0.f;
#pragma unroll
    for (int i = 0; i < 4; i++) { vals[i] = xr[t + 256 * i]; s += vals[i]; }
    float mu = blockReduce256(s) * (1.f / NI);
    float s2 = 0.f;
#pragma unroll
    for (int i = 0; i < 4; i++) { float d = vals[i] - mu; s2 += d * d; }
    float var = blockReduce256(s2) * (1.f / NI);
    float rs = rsqrtf(var + EPS);
#pragma unroll
    for (int i = 0; i < 4; i++) {
        int c = t + 256 * i;
        g_xn[bi * NI + c] = (vals[i] - mu) * rs * w[c] + b[c];
    }
}

// ---------------- tensor-core split-K GEMM: 64(M) x 128(N) tile ----------------
// bf16x3 split (hi/lo), mma.m16n8k16. conv=1: W'[k][n] = Wc[(n*2048+k)*4+3].
struct GJob {
    const float* A; const float* W; float* P;
    int K, kc, N, conv;
};

__global__ __launch_bounds__(256, 2) void gemm_t(GJob j0, GJob j1) {
    GJob j = blockIdx.z ? j1 : j0;
    __shared__ __align__(16) uint32_t Aph[16][72];
    __shared__ __align__(16) uint32_t Apl[16][72];
    __shared__ __align__(16) uint32_t Wph[16][136];
    __shared__ __align__(16) uint32_t Wpl[16][136];

    const int tid = threadIdx.x;
    const int n0 = blockIdx.x * 128;
    const int k0 = blockIdx.y * j.kc;
    const int nst = j.kc >> 5;
    float* P = j.P + (size_t)blockIdx.y * 64 * j.N;

    const int lane = tid & 31;
    const int warp = tid >> 5;
    const int g = lane >> 2, tg = lane & 3;
    const int wm = warp & 3, wn = warp >> 2;     // 4 warps M x 2 warps N

    // A staging map: m = tid>>2, k-offset = (tid&3)*8, 2 float4
    const int am = tid >> 2;
    const int ak = (tid & 3) * 8;
    // conv staging map: n = tid>>1, k-quarter = (tid&1)*16
    const int cn = tid >> 1;
    const int ckq = (tid & 1) * 16;

    float4 av0, av1;
    float wv[16];
    float acc[8][4] = {};

    // ---------- stage-0 loads ----------
    {
        int kb = k0;
        const float* Ap = j.A + (size_t)am * j.K + kb + ak;
        av0 = *(const float4*)(Ap);
        av1 = *(const float4*)(Ap + 4);
        if (!j.conv) {
#pragma unroll
            for (int r = 0; r < 2; r++) {
                int e = tid + r * 256;
                int kp = e >> 5, n4 = e & 31;
                float4 r0 = *(const float4*)(j.W + (size_t)(kb + 2 * kp) * j.N + n0 + n4 * 4);
                float4 r1 = *(const float4*)(j.W + (size_t)(kb + 2 * kp + 1) * j.N + n0 + n4 * 4);
                wv[r * 8 + 0] = r0.x; wv[r * 8 + 1] = r0.y; wv[r * 8 + 2] = r0.z; wv[r * 8 + 3] = r0.w;
                wv[r * 8 + 4] = r1.x; wv[r * 8 + 5] = r1.y; wv[r * 8 + 6] = r1.z; wv[r * 8 + 7] = r1.w;
            }
        } else {
            const float* base = j.W + 3;
#pragma unroll
            for (int i = 0; i < 16; i++)
                wv[i] = base[((size_t)(n0 + cn) * 2048 + kb + ckq + i) * 4];
        }
    }
    // ---------- stage-0 store ----------
    {
        int p0 = ak >> 1;
        pack_hl(av0.x, av0.y, Aph[p0 + 0][am], Apl[p0 + 0][am]);
        pack_hl(av0.z, av0.w, Aph[p0 + 1][am], Apl[p0 + 1][am]);
        pack_hl(av1.x, av1.y, Aph[p0 + 2][am], Apl[p0 + 2][am]);
        pack_hl(av1.z, av1.w, Aph[p0 + 3][am], Apl[p0 + 3][am]);
        if (!j.conv) {
#pragma unroll
            for (int r = 0; r < 2; r++) {
                int e = tid + r * 256;
                int kp = e >> 5, n4 = e & 31;
                uint4 hi, lo;
                pack_hl(wv[r * 8 + 0], wv[r * 8 + 4], hi.x, lo.x);
                pack_hl(wv[r * 8 + 1], wv[r * 8 + 5], hi.y, lo.y);
                pack_hl(wv[r * 8 + 2], wv[r * 8 + 6], hi.z, lo.z);
                pack_hl(wv[r * 8 + 3], wv[r * 8 + 7], hi.w, lo.w);
                *(uint4*)&Wph[kp][n4 * 4] = hi;
                *(uint4*)&Wpl[kp][n4 * 4] = lo;
            }
        } else {
            int kp0 = ckq >> 1;
#pragma unroll
            for (int i = 0; i < 8; i++)
                pack_hl(wv[2 * i], wv[2 * i + 1], Wph[kp0 + i][cn], Wpl[kp0 + i][cn]);
        }
    }
    __syncthreads();

    for (int s = 0; s < nst; s++) {
        // ---- prefetch next stage into regs ----
        if (s + 1 < nst) {
            int kb = k0 + (s + 1) * 32;
            const float* Ap = j.A + (size_t)am * j.K + kb + ak;
            av0 = *(const float4*)(Ap);
            av1 = *(const float4*)(Ap + 4);
            if (!j.conv) {
#pragma unroll
                for (int r = 0; r < 2; r++) {
                    int e = tid + r * 256;
                    int kp = e >> 5, n4 = e & 31;
                    float4 r0 = *(const float4*)(j.W + (size_t)(kb + 2 * kp) * j.N + n0 + n4 * 4);
                    float4 r1 = *(const float4*)(j.W + (size_t)(kb + 2 * kp + 1) * j.N + n0 + n4 * 4);
                    wv[r * 8 + 0] = r0.x; wv[r * 8 + 1] = r0.y; wv[r * 8 + 2] = r0.z; wv[r * 8 + 3] = r0.w;
                    wv[r * 8 + 4] = r1.x; wv[r * 8 + 5] = r1.y; wv[r * 8 + 6] = r1.z; wv[r * 8 + 7] = r1.w;
                }
            } else {
                const float* base = j.W + 3;
#pragma unroll
                for (int i = 0; i < 16; i++)
                    wv[i] = base[((size_t)(n0 + cn) * 2048 + kb + ckq + i) * 4];
            }
        }
        // ---- compute on current smem stage: 2 k16 steps ----
#pragma unroll
        for (int st = 0; st < 2; st++) {
            int kr = st * 8;
            int mrow = wm * 16 + g;
            uint32_t a0h = Aph[kr + tg][mrow];
            uint32_t a1h = Aph[kr + tg][mrow + 8];
            uint32_t a2h = Aph[kr + tg + 4][mrow];
            uint32_t a3h = Aph[kr + tg + 4][mrow + 8];
            uint32_t a0l = Apl[kr + tg][mrow];
            uint32_t a1l = Apl[kr + tg][mrow + 8];
            uint32_t a2l = Apl[kr + tg + 4][mrow];
            uint32_t a3l = Apl[kr + tg + 4][mrow + 8];
#pragma unroll
            for (int jt = 0; jt < 8; jt++) {
                int col = wn * 64 + jt * 8 + g;
                uint32_t b0h = Wph[kr + tg][col];
                uint32_t b1h = Wph[kr + tg + 4][col];
                uint32_t b0l = Wpl[kr + tg][col];
                uint32_t b1l = Wpl[kr + tg + 4][col];
                mma_bf16(acc[jt], a0h, a1h, a2h, a3h, b0h, b1h);
                mma_bf16(acc[jt], a0h, a1h, a2h, a3h, b0l, b1l);
                mma_bf16(acc[jt], a0l, a1l, a2l, a3l, b0h, b1h);
            }
        }
        __syncthreads();
        // ---- store next stage ----
        if (s + 1 < nst) {
            int p0 = ak >> 1;
            pack_hl(av0.x, av0.y, Aph[p0 + 0][am], Apl[p0 + 0][am]);
            pack_hl(av0.z, av0.w, Aph[p0 + 1][am], Apl[p0 + 1][am]);
            pack_hl(av1.x, av1.y, Aph[p0 + 2][am], Apl[p0 + 2][am]);
            pack_hl(av1.z, av1.w, Aph[p0 + 3][am], Apl[p0 + 3][am]);
            if (!j.conv) {
#pragma unroll
                for (int r = 0; r < 2; r++) {
                    int e = tid + r * 256;
                    int kp = e >> 5, n4 = e & 31;
                    uint4 hi, lo;
                    pack_hl(wv[r * 8 + 0], wv[r * 8 + 4], hi.x, lo.x);
                    pack_hl(wv[r * 8 + 1], wv[r * 8 + 5], hi.y, lo.y);
                    pack_hl(wv[r * 8 + 2], wv[r * 8 + 6], hi.z, lo.z);
                    pack_hl(wv[r * 8 + 3], wv[r * 8 + 7], hi.w, lo.w);
                    *(uint4*)&Wph[kp][n4 * 4] = hi;
                    *(uint4*)&Wpl[kp][n4 * 4] = lo;
                }
            } else {
                int kp0 = ckq >> 1;
#pragma unroll
                for (int i = 0; i < 8; i++)
                    pack_hl(wv[2 * i], wv[2 * i + 1], Wph[kp0 + i][cn], Wpl[kp0 + i][cn]);
            }
            __syncthreads();
        }
    }

    // ---- write partials ----
#pragma unroll
    for (int jt = 0; jt < 8; jt++) {
        int col = n0 + wn * 64 + jt * 8 + tg * 2;
        int row0 = wm * 16 + g;
        *(float2*)(P + (size_t)row0 * j.N + col) = make_float2(acc[jt][0], acc[jt][1]);
        *(float2*)(P + (size_t)(row0 + 8) * j.N + col) = make_float2(acc[jt][2], acc[jt][3]);
    }
}

// ---------------- float4 split-K reduce + epilogue, dual-job ----------------
struct RJob {
    const float4* P; int np;
    const float4* bias; float4* C;
    int mode; const float4* R; int N4;
};

__global__ __launch_bounds__(256) void reduce_k(RJob r0, RJob r1) {
    RJob r = blockIdx.z ? r1 : r0;
    int idx = blockIdx.x * 256 + threadIdx.x;
    int total = 64 * r.N4;
    if (idx >= total) return;
    int n4 = idx % r.N4;
    float4 s = make_float4(0.f, 0.f, 0.f, 0.f);
#pragma unroll 4
    for (int p = 0; p < r.np; p++) {
        float4 v = r.P[(size_t)p * total + idx];
        s.x += v.x; s.y += v.y; s.z += v.z; s.w += v.w;
    }
    float4 b = r.bias[n4];
    s.x += b.x; s.y += b.y; s.z += b.z; s.w += b.w;
    if (r.mode == 1) {
        s.x = siluf_(s.x); s.y = siluf_(s.y); s.z = siluf_(s.z); s.w = siluf_(s.w);
    } else if (r.mode == 2) {
        s.x = sigmoidf_(s.x); s.y = sigmoidf_(s.y); s.z = sigmoidf_(s.z); s.w = sigmoidf_(s.w);
    } else if (r.mode == 3) {
        float4 rv = r.R[idx];
        s.x += rv.x; s.y += rv.y; s.z += rv.z; s.w += rv.w;
    }
    r.C[idx] = s;
}

// ---------------- block-diagonal q/k/v: tile 32(m) x 64(n), 128 thr ----------------
__global__ __launch_bounds__(128) void qkv_kernel(const float* __restrict__ Wq,
                                                  const float* __restrict__ Wk,
                                                  const float* __restrict__ Wv,
                                                  const float* __restrict__ bq,
                                                  const float* __restrict__ bk,
                                                  const float* __restrict__ bv) {
    int z = blockIdx.z;
    int which = z >> 3, h = z & 7;
    const float* A = (which == 2) ? g_xl : g_xc;
    const float* W; const float* bias; float* C; float scale = 1.f;
    if (which == 0) { W = Wq; bias = bq; C = g_q; }
    else if (which == 1) { W = Wk; bias = bk; C = g_k; scale = 0.0625f; }
    else { W = Wv; bias = bv; C = g_v; }
    W += (size_t)h * ND * ND;
    bias += h * ND;
    int n0 = blockIdx.x * 64;
    int m0 = blockIdx.y * 32;
    __shared__ __align__(16) float As[32][36];
    __shared__ __align__(16) float Ws[32][68];
    int tx = threadIdx.x & 15, ty = threadIdx.x >> 4;
    float acc[4][4] = {};
    for (int kb = 0; kb < ND; kb += 32) {
#pragma unroll
        for (int r = 0; r < 2; r++) {
            int ee = threadIdx.x + r * 128;
            int k4 = ee & 7, m = ee >> 3;
            float4 v = *(const float4*)(A + (size_t)(m0 + m) * NHID + h * ND + kb + 4 * k4);
            *(float4*)&As[m][4 * k4] = v;
        }
#pragma unroll
        for (int r = 0; r < 4; r++) {
            int ee = threadIdx.x + r * 128;
            int n4 = ee & 15, k = ee >> 4;
            float4 v = *(const float4*)(W + (size_t)(kb + k) * ND + n0 + 4 * n4);
            *(float4*)&Ws[k][4 * n4] = v;
        }
        __syncthreads();
#pragma unroll
        for (int kk = 0; kk < 32; kk++) {
            float4 w = *(const float4*)&Ws[kk][tx * 4];
            float a0 = As[ty * 4 + 0][kk];
            float a1 = As[ty * 4 + 1][kk];
            float a2 = As[ty * 4 + 2][kk];
            float a3 = As[ty * 4 + 3][kk];
            acc[0][0] += a0 * w.x; acc[0][1] += a0 * w.y; acc[0][2] += a0 * w.z; acc[0][3] += a0 * w.w;
            acc[1][0] += a1 * w.x; acc[1][1] += a1 * w.y; acc[1][2] += a1 * w.z; acc[1][3] += a1 * w.w;
            acc[2][0] += a2 * w.x; acc[2][1] += a2 * w.y; acc[2][2] += a2 * w.z; acc[2][3] += a2 * w.w;
            acc[3][0] += a3 * w.x; acc[3][1] += a3 * w.y; acc[3][2] += a3 * w.z; acc[3][3] += a3 * w.w;
        }
        __syncthreads();
    }
#pragma unroll
    for (int i = 0; i < 4; i++) {
        int m = m0 + ty * 4 + i;
        int n = n0 + tx * 4;
        float4 b4 = *(const float4*)(bias + n);
        float4 v = make_float4((acc[i][0] + b4.x) * scale, (acc[i][1] + b4.y) * scale,
                               (acc[i][2] + b4.z) * scale, (acc[i][3] + b4.w) * scale);
        *(float4*)(C + (size_t)m * NHID + h * ND + n) = v;
    }
}

// ---------------- i/f gate GEMVs + stabilized exp gating ----------------
__global__ __launch_bounds__(256) void gates_kernel(const float* __restrict__ Wi,
                                                    const float* __restrict__ bi,
                                                    const float* __restrict__ Wf,
                                                    const float* __restrict__ bf,
                                                    const float* __restrict__ m_prev,
                                                    float* __restrict__ m_out) {
    int b = blockIdx.x, t = threadIdx.x;
    float pi[8] = {}, pf[8] = {};
    for (int k = t; k < NHID; k += 256) {
        float xv = g_xc[b * NHID + k];
        const float4* wi4 = (const float4*)(Wi + k * 8);
        const float4* wf4 = (const float4*)(Wf + k * 8);
        float4 a0 = wi4[0], a1 = wi4[1], f0 = wf4[0], f1 = wf4[1];
        pi[0] += xv * a0.x; pi[1] += xv * a0.y; pi[2] += xv * a0.z; pi[3] += xv * a0.w;
        pi[4] += xv * a1.x; pi[5] += xv * a1.y; pi[6] += xv * a1.z; pi[7] += xv * a1.w;
        pf[0] += xv * f0.x; pf[1] += xv * f0.y; pf[2] += xv * f0.z; pf[3] += xv * f0.w;
        pf[4] += xv * f1.x; pf[5] += xv * f1.y; pf[6] += xv * f1.z; pf[7] += xv * f1.w;
    }
    __shared__ float s[256 * 16];
#pragma unroll
    for (int h = 0; h < 8; h++) { s[t * 16 + h] = pi[h]; s[t * 16 + 8 + h] = pf[h]; }
    __syncthreads();
    if (t < 16) {
        float a = 0.f;
        for (int r = 0; r < 256; r++) a += s[r * 16 + t];
        s[t] = a;
    }
    __syncthreads();
    if (t < 8) {
        float it = s[t] + bi[t];
        float ft = s[8 + t] + bf[t];
        float mp = m_prev[b * 8 + t];
        float m = fmaxf(ft + mp, it);
        m_out[b * 8 + t] = m;
        g_ig[b * 8 + t] = expf(it - m);
        g_fg[b * 8 + t] = expf(ft + mp - m);
    }
}

// ---------------- fused state update + readout + GroupNorm + gating ----------------
__global__ __launch_bounds__(256) void state_kernel(const float* __restrict__ c_prev,
                                                    const float* __restrict__ n_prev,
                                                    const float* __restrict__ gn_w,
                                                    const float* __restrict__ gn_b,
                                                    float* __restrict__ c_out,
                                                    float* __restrict__ n_out,
                                                    float* __restrict__ h_out) {
    int bh = blockIdx.x;
    int b = bh >> 3, h = bh & 7;
    int t = threadIdx.x;
    __shared__ __align__(16) float qs[256], ks[256], vs[256], hts[256];
    __shared__ float den_s;
    float fg = g_fg[bh], ig = g_ig[bh];
    int base = bh * ND;
    float qv = g_q[base + t], kv = g_k[base + t], vv = g_v[base + t];
    qs[t] = qv; ks[t] = kv; vs[t] = vv;
    float nt = fg * n_prev[base + t] + ig * kv;
    n_out[base + t] = nt;
    float den = blockReduce256(nt * qv);
    if (t == 0) den_s = fmaxf(den, 1.f);
    __syncthreads();
    den = den_s;
    int w = t >> 5, lane = t & 31;
    const float4* cp4 = (const float4*)(c_prev + (size_t)bh * ND * ND);
    float4* ct4 = (float4*)(c_out + (size_t)bh * ND * ND);
    const float4* qs4 = (const float4*)qs;
    const float4* ks4 = (const float4*)ks;
    for (int d0 = w * 32; d0 < w * 32 + 32; d0 += 4) {
        float acc0 = 0.f, acc1 = 0.f, acc2 = 0.f, acc3 = 0.f;
        float vd0 = vs[d0 + 0] * ig, vd1 = vs[d0 + 1] * ig;
        float vd2 = vs[d0 + 2] * ig, vd3 = vs[d0 + 3] * ig;
#pragma unroll
        for (int p = 0; p < 2; p++) {
            int ci = lane + p * 32;
            float4 kk = ks4[ci];
            float4 qq = qs4[ci];
            float4 cp0 = cp4[(size_t)(d0 + 0) * 64 + ci];
            float4 cp1 = cp4[(size_t)(d0 + 1) * 64 + ci];
            float4 cp2 = cp4[(size_t)(d0 + 2) * 64 + ci];
            float4 cp3 = cp4[(size_t)(d0 + 3) * 64 + ci];
            float4 c0, c1, c2, c3;
            c0.x = fg * cp0.x + vd0 * kk.x; c0.y = fg * cp0.y + vd0 * kk.y;
            c0.z = fg * cp0.z + vd0 * kk.z; c0.w = fg * cp0.w + vd0 * kk.w;
            c1.x = fg * cp1.x + vd1 * kk.x; c1.y = fg * cp1.y + vd1 * kk.y;
            c1.z = fg * cp1.z + vd1 * kk.z; c1.w = fg * cp1.w + vd1 * kk.w;
            c2.x = fg * cp2.x + vd2 * kk.x; c2.y = fg * cp2.y + vd2 * kk.y;
            c2.z = fg * cp2.z + vd2 * kk.z; c2.w = fg * cp2.w + vd2 * kk.w;
            c3.x = fg * cp3.x + vd3 * kk.x; c3.y = fg * cp3.y + vd3 * kk.y;
            c3.z = fg * cp3.z + vd3 * kk.z; c3.w = fg * cp3.w + vd3 * kk.w;
            ct4[(size_t)(d0 + 0) * 64 + ci] = c0;
            ct4[(size_t)(d0 + 1) * 64 + ci] = c1;
            ct4[(size_t)(d0 + 2) * 64 + ci] = c2;
            ct4[(size_t)(d0 + 3) * 64 + ci] = c3;
            acc0 += c0.x * qq.x + c0.y * qq.y + c0.z * qq.z + c0.w * qq.w;
            acc1 += c1.x * qq.x + c1.y * qq.y + c1.z * qq.z + c1.w * qq.w;
            acc2 += c2.x * qq.x + c2.y * qq.y + c2.z * qq.z + c2.w * qq.w;
            acc3 += c3.x * qq.x + c3.y * qq.y + c3.z * qq.z + c3.w * qq.w;
        }
#pragma unroll
        for (int off = 16; off > 0; off >>= 1) {
            acc0 += __shfl_xor_sync(0xffffffffu, acc0, off);
            acc1 += __shfl_xor_sync(0xffffffffu, acc1, off);
            acc2 += __shfl_xor_sync(0xffffffffu, acc2, off);
            acc3 += __shfl_xor_sync(0xffffffffu, acc3, off);
        }
        if (lane == 0) {
            float h0 = g_o[base + d0 + 0] * acc0 / den;
            float h1 = g_o[base + d0 + 1] * acc1 / den;
            float h2 = g_o[base + d0 + 2] * acc2 / den;
            float h3 = g_o[base + d0 + 3] * acc3 / den;
            hts[d0 + 0] = h0; hts[d0 + 1] = h1; hts[d0 + 2] = h2; hts[d0 + 3] = h3;
            h_out[base + d0 + 0] = h0; h_out[base + d0 + 1] = h1;
            h_out[base + d0 + 2] = h2; h_out[base + d0 + 3] = h3;
        }
    }
    __syncthreads();
    float hv = hts[t];
    float mu = blockReduce256(hv) * (1.f / ND);
    float dv = hv - mu;
    float var = blockReduce256(dv * dv) * (1.f / ND);
    float g = dv * rsqrtf(var + EPS);
    int hid = h * ND + t;
    float xrv = g_xr[b * NHID + hid];
    g_outpre[b * NHID + hid] =
        (g * gn_w[hid] + gn_b[hid] + g_xskip[b * NHID + hid]) * siluf_(xrv);
}

// ---------------- host launcher ----------------
extern "C" void kernel_launch(void* const* d_in, const int* in_sizes, int n_in,
                              void* d_out, int out_size) {
    (void)in_sizes; (void)n_in; (void)out_size;
    const float* x      = (const float*)d_in[0];
    const float* c_prev = (const float*)d_in[2];
    const float* n_prev = (const float*)d_in[3];
    const float* m_prev = (const float*)d_in[4];
    const float* ln_w   = (const float*)d_in[5];
    const float* ln_b   = (const float*)d_in[6];
    const float* W_ul   = (const float*)d_in[7];
    const float* b_ul   = (const float*)d_in[8];
    const float* W_ur   = (const float*)d_in[9];
    const float* b_ur   = (const float*)d_in[10];
    const float* W_conv = (const float*)d_in[11];
    const float* b_conv = (const float*)d_in[12];
    const float* W_skip = (const float*)d_in[13];
    const float* b_skip = (const float*)d_in[14];
    const float* W_q    = (const float*)d_in[15];
    const float* b_q    = (const float*)d_in[16];
    const float* W_k    = (const float*)d_in[17];
    const float* b_k    = (const float*)d_in[18];
    const float* W_v    = (const float*)d_in[19];
    const float* b_v    = (const float*)d_in[20];
    const float* W_i    = (const float*)d_in[21];
    const float* b_i    = (const float*)d_in[22];
    const float* W_f    = (const float*)d_in[23];
    const float* b_f    = (const float*)d_in[24];
    const float* W_o    = (const float*)d_in[25];
    const float* b_o    = (const float*)d_in[26];
    const float* W_down = (const float*)d_in[27];
    const float* b_down = (const float*)d_in[28];
    const float* gn_w   = (const float*)d_in[29];
    const float* gn_b   = (const float*)d_in[30];

    float* out = (float*)d_out;
    float* out_final = out;
    float* out_h = out + NB * NI;
    float* out_c = out_h + NB * NH * ND;
    float* out_n = out_c + (size_t)NB * NH * ND * ND;
    float* out_m = out_n + NB * NH * ND;

    void *p_xn, *p_xl, *p_xr, *p_xc, *p_xskip, *p_o, *p_outpre, *p_part;
    cudaGetSymbolAddress(&p_xn, g_xn);
    cudaGetSymbolAddress(&p_xl, g_xl);
    cudaGetSymbolAddress(&p_xr, g_xr);
    cudaGetSymbolAddress(&p_xc, g_xc);
    cudaGetSymbolAddress(&p_xskip, g_xskip);
    cudaGetSymbolAddress(&p_o, g_o);
    cudaGetSymbolAddress(&p_outpre, g_outpre);
    cudaGetSymbolAddress(&p_part, g_part);
    float* xn = (float*)p_xn;
    float* xl = (float*)p_xl;
    float* xr = (float*)p_xr;
    float* xc = (float*)p_xc;
    float* xskip = (float*)p_xskip;
    float* o = (float*)p_o;
    float* outpre = (float*)p_outpre;
    float* part = (float*)p_part;

    const int SLOT = NB * NHID;

    // 1. LayerNorm
    ln_kernel<<<NB, 256>>>(x, ln_w, ln_b);

    // 2. xl / xr : K=1024, 8-way split
    {
        GJob a{xn, W_ul, part, NI, 128, NHID, 0};
        GJob b2{xn, W_ur, part + (size_t)8 * SLOT, NI, 128, NHID, 0};
        gemm_t<<<dim3(16, 8, 2), 256>>>(a, b2);
        RJob ra{(const float4*)part, 8, (const float4*)b_ul, (float4*)xl, 0, nullptr, NHID / 4};
        RJob rb{(const float4*)(part + (size_t)8 * SLOT), 8, (const float4*)b_ur, (float4*)xr, 0, nullptr, NHID / 4};
        reduce_k<<<dim3(128, 1, 2), 256>>>(ra, rb);
    }

    // 3. conv + o-pre : K=2048, 8-way split
    {
        GJob a{xl, W_conv, part, NHID, 256, NHID, 1};
        GJob b2{xl, W_o, part + (size_t)8 * SLOT, NHID, 256, NHID, 0};
        gemm_t<<<dim3(16, 8, 2), 256>>>(a, b2);
        RJob ra{(const float4*)part, 8, (const float4*)b_conv, (float4*)xc, 1, nullptr, NHID / 4};
        RJob rb{(const float4*)(part + (size_t)8 * SLOT), 8, (const float4*)b_o, (float4*)o, 2, nullptr, NHID / 4};
        reduce_k<<<dim3(128, 1, 2), 256>>>(ra, rb);
    }

    // 4. skip GEMM (16-way split) + qkv + gates
    {
        GJob a{xc, W_skip, part, NHID, 128, NHID, 0};
        gemm_t<<<dim3(16, 16, 1), 256>>>(a, a);
        qkv_kernel<<<dim3(4, 2, 24), 128>>>(W_q, W_k, W_v, b_q, b_k, b_v);
        gates_kernel<<<NB, 256>>>(W_i, b_i, W_f, b_f, m_prev, out_m);
        RJob ra{(const float4*)part, 16, (const float4*)b_skip, (float4*)xskip, 0, nullptr, NHID / 4};
        reduce_k<<<dim3(128, 1, 1), 256>>>(ra, ra);
    }

    // 5. fused state update / readout / groupnorm / gating
    state_kernel<<<NB * NH, 256>>>(c_prev, n_prev, gn_w, gn_b, out_c, out_n, out_h);

    // 6. final = outpre @ W_down + b_down + x : K=2048, 32-way split, N=1024
    {
        GJob a{outpre, W_down, part, NHID, 64, NI, 0};
        gemm_t<<<dim3(8, 32, 1), 256>>>(a, a);
        RJob ra{(const float4*)part, 32, (const float4*)b_down, (float4*)out_final, 3, (const float4*)x, NI / 4};
        reduce_k<<<dim3(64, 1, 1), 256>>>(ra, ra);
    }
}

// round 5
// speedup vs baseline: 1.8369x; 1.0405x over previous
#include <cuda_runtime.h>
#include <cuda_bf16.h>
#include <math.h>
#include <stdint.h>

#define NB   64
#define NI   1024
#define NHID 2048
#define NH   8
#define ND   256
#define EPS  1e-5f

// ---------------- device scratch ----------------
__device__ float g_xn[NB * NI];
__device__ float g_xl[NB * NHID];
__device__ float g_xr[NB * NHID];
__device__ float g_xc[NB * NHID];
__device__ float g_xskip[NB * NHID];
__device__ float g_o[NB * NHID];
__device__ float g_q[NB * NHID];
__device__ float g_k[NB * NHID];
__device__ float g_v[NB * NHID];
__device__ float g_outpre[NB * NHID];
__device__ float g_ig[NB * NH];
__device__ float g_fg[NB * NH];
__device__ float g_part[16 * NB * NHID];        // split-K partial slots (8MB)
__device__ uint32_t g_wch[1024 * 2048];         // conv tap3, bf16x2 hi plane [k/2][n]
__device__ uint32_t g_wcl[1024 * 2048];         // conv tap3, bf16x2 lo plane

// ---------------- helpers ----------------
__device__ __forceinline__ float blockReduce256(float v) {
    __shared__ float red[256];
    int t = threadIdx.x;
    red[t] = v;
    __syncthreads();
#pragma unroll
    for (int s = 128; s > 0; s >>= 1) {
        if (t < s) red[t] += red[t + s];
        __syncthreads();
    }
    float r = red[0];
    __syncthreads();
    return r;
}
__device__ __forceinline__ float sigmoidf_(float x) { return 1.f / (1.f + expf(-x)); }
__device__ __forceinline__ float siluf_(float x) { return x / (1.f + expf(-x)); }

// split a float pair into bf16x2 hi and lo words (low half = first element)
__device__ __forceinline__ void pack_hl(float x, float y, uint32_t& hi, uint32_t& lo) {
    __nv_bfloat162 h = __float22bfloat162_rn(make_float2(x, y));
    float2 hf = __bfloat1622float2(h);
    __nv_bfloat162 l = __float22bfloat162_rn(make_float2(x - hf.x, y - hf.y));
    hi = *(uint32_t*)&h;
    lo = *(uint32_t*)&l;
}

__device__ __forceinline__ void mma_bf16(float* acc, uint32_t a0, uint32_t a1,
                                         uint32_t a2, uint32_t a3,
                                         uint32_t b0, uint32_t b1) {
    asm volatile(
        "mma.sync.aligned.m16n8k16.row.col.f32.bf16.bf16.f32 "
        "{%0,%1,%2,%3}, {%4,%5,%6,%7}, {%8,%9}, {%0,%1,%2,%3};"
        : "+f"(acc[0]), "+f"(acc[1]), "+f"(acc[2]), "+f"(acc[3])
        : "r"(a0), "r"(a1), "r"(a2), "r"(a3), "r"(b0), "r"(b1));
}

// ---------------- prepack W_conv tap-3 -> dense bf16 hi/lo planes ----------------
// source: Wc[(n*2048 + k)*4 + 3]   dest word (kp, n) = pack(tap3[2kp][n], tap3[2kp+1][n])
__global__ __launch_bounds__(256) void prep_conv(const float* __restrict__ Wc) {
    __shared__ float tile[32][33];
    int k0 = blockIdx.x * 32, n0 = blockIdx.y * 32;
    int t = threadIdx.x;
#pragma unroll
    for (int r = 0; r < 4; r++) {
        int id = t + r * 256;
        int n = id >> 5, k = id & 31;
        tile[n][k] = Wc[((size_t)(n0 + n) * 2048 + k0 + k) * 4 + 3];
    }
    __syncthreads();
#pragma unroll
    for (int r = 0; r < 2; r++) {
        int id = t + r * 256;
        int kp = id >> 5, n = id & 31;
        uint32_t hi, lo;
        pack_hl(tile[n][2 * kp], tile[n][2 * kp + 1], hi, lo);
        size_t off = (size_t)(k0 / 2 + kp) * 2048 + n0 + n;
        g_wch[off] = hi;
        g_wcl[off] = lo;
    }
}

// ---------------- LayerNorm ----------------
__global__ __launch_bounds__(256) void ln_kernel(const float* __restrict__ x,
                                                 const float* __restrict__ w,
                                                 const float* __restrict__ b) {
    int bi = blockIdx.x, t = threadIdx.x;
    const float* xr = x + bi * NI;
    float vals[4];
    float s = 0.f;
#pragma unroll
    for (int i = 0; i < 4; i++) { vals[i] = xr[t + 256 * i]; s += vals[i]; }
    float mu = blockReduce256(s) * (1.f / NI);
    float s2 = 0.f;
#pragma unroll
    for (int i = 0; i < 4; i++) { float d = vals[i] - mu; s2 += d * d; }
    float var = blockReduce256(s2) * (1.f / NI);
    float rs = rsqrtf(var + EPS);
#pragma unroll
    for (int i = 0; i < 4; i++) {
        int c = t + 256 * i;
        g_xn[bi * NI + c] = (vals[i] - mu) * rs * w[c] + b[c];
    }
}

// ---------------- tensor-core split-K GEMM: 64(M) x 128(N) tile, double-buffered ----
// wfmt=0: W fp32 [K][N]; wfmt=1: W prepacked bf16 hi/lo planes [K/2][N] (Wh/Wl)
struct GJob {
    const float* A; const float* W;
    const uint32_t* Wh; const uint32_t* Wl;
    float* P;
    int K, kc, N, wfmt;
};

// dynamic smem layout (uint32 words):
//  Aph [2][16][72]  @ 0      (2304)
//  Apl [2][16][72]  @ 2304
//  Wph [2][16][136] @ 4608   (4352)
//  Wpl [2][16][136] @ 8960   ; total 13312 words = 53248 B
#define SMEM_WORDS 13312

__global__ __launch_bounds__(256, 2) void gemm_t(GJob j0, GJob j1) {
    GJob j = blockIdx.z ? j1 : j0;
    extern __shared__ __align__(16) uint32_t sm[];
    typedef uint32_t (*A72)[72];
    typedef uint32_t (*W136)[136];

    const int tid = threadIdx.x;
    const int n0 = blockIdx.x * 128;
    const int k0 = blockIdx.y * j.kc;
    const int nst = j.kc >> 5;
    float* P = j.P + (size_t)blockIdx.y * 64 * j.N;

    const int lane = tid & 31;
    const int warp = tid >> 5;
    const int g = lane >> 2, tg = lane & 3;
    const int wm = warp & 3, wn = warp >> 2;     // 4 warps M x 2 warps N

    // A staging map: m = tid>>2, k-offset = (tid&3)*8
    const int am = tid >> 2;
    const int ak = (tid & 3) * 8;

    float4 av0, av1;
    float wv[16];
    uint4 wh[2], wl[2];
    float acc[8][4] = {};

    // ---- load stage (gmem -> regs) ----
    auto load = [&](int kb) {
        const float* Ap = j.A + (size_t)am * j.K + kb + ak;
        av0 = *(const float4*)(Ap);
        av1 = *(const float4*)(Ap + 4);
        if (j.wfmt == 0) {
#pragma unroll
            for (int r = 0; r < 2; r++) {
                int e = tid + r * 256;
                int kp = e >> 5, n4 = e & 31;
                float4 r0 = *(const float4*)(j.W + (size_t)(kb + 2 * kp) * j.N + n0 + n4 * 4);
                float4 r1 = *(const float4*)(j.W + (size_t)(kb + 2 * kp + 1) * j.N + n0 + n4 * 4);
                wv[r * 8 + 0] = r0.x; wv[r * 8 + 1] = r0.y; wv[r * 8 + 2] = r0.z; wv[r * 8 + 3] = r0.w;
                wv[r * 8 + 4] = r1.x; wv[r * 8 + 5] = r1.y; wv[r * 8 + 6] = r1.z; wv[r * 8 + 7] = r1.w;
            }
        } else {
#pragma unroll
            for (int r = 0; r < 2; r++) {
                int e = tid + r * 256;
                int kp = e >> 5, n16 = e & 31;
                size_t off = (size_t)((kb >> 1) + kp) * 2048 + n0 + n16 * 4;
                wh[r] = *(const uint4*)&j.Wh[off];
                wl[r] = *(const uint4*)&j.Wl[off];
            }
        }
    };

    // ---- store stage (regs -> smem buffer) ----
    auto store = [&](int buf) {
        A72 aph = (A72)(sm + buf * 16 * 72);
        A72 apl = (A72)(sm + 2304 + buf * 16 * 72);
        W136 wph = (W136)(sm + 4608 + buf * 16 * 136);
        W136 wpl = (W136)(sm + 8960 + buf * 16 * 136);
        int p0 = ak >> 1;
        pack_hl(av0.x, av0.y, aph[p0 + 0][am], apl[p0 + 0][am]);
        pack_hl(av0.z, av0.w, aph[p0 + 1][am], apl[p0 + 1][am]);
        pack_hl(av1.x, av1.y, aph[p0 + 2][am], apl[p0 + 2][am]);
        pack_hl(av1.z, av1.w, aph[p0 + 3][am], apl[p0 + 3][am]);
        if (j.wfmt == 0) {
#pragma unroll
            for (int r = 0; r < 2; r++) {
                int e = tid + r * 256;
                int kp = e >> 5, n4 = e & 31;
                uint4 hi, lo;
                pack_hl(wv[r * 8 + 0], wv[r * 8 + 4], hi.x, lo.x);
                pack_hl(wv[r * 8 + 1], wv[r * 8 + 5], hi.y, lo.y);
                pack_hl(wv[r * 8 + 2], wv[r * 8 + 6], hi.z, lo.z);
                pack_hl(wv[r * 8 + 3], wv[r * 8 + 7], hi.w, lo.w);
                *(uint4*)&wph[kp][n4 * 4] = hi;
                *(uint4*)&wpl[kp][n4 * 4] = lo;
            }
        } else {
#pragma unroll
            for (int r = 0; r < 2; r++) {
                int e = tid + r * 256;
                int kp = e >> 5, n16 = e & 31;
                *(uint4*)&wph[kp][n16 * 4] = wh[r];
                *(uint4*)&wpl[kp][n16 * 4] = wl[r];
            }
        }
    };

    // ---- compute on a smem buffer ----
    auto compute = [&](int buf) {
        A72 aph = (A72)(sm + buf * 16 * 72);
        A72 apl = (A72)(sm + 2304 + buf * 16 * 72);
        W136 wph = (W136)(sm + 4608 + buf * 16 * 136);
        W136 wpl = (W136)(sm + 8960 + buf * 16 * 136);
#pragma unroll
        for (int st = 0; st < 2; st++) {
            int kr = st * 8;
            int mrow = wm * 16 + g;
            uint32_t a0h = aph[kr + tg][mrow];
            uint32_t a1h = aph[kr + tg][mrow + 8];
            uint32_t a2h = aph[kr + tg + 4][mrow];
            uint32_t a3h = aph[kr + tg + 4][mrow + 8];
            uint32_t a0l = apl[kr + tg][mrow];
            uint32_t a1l = apl[kr + tg][mrow + 8];
            uint32_t a2l = apl[kr + tg + 4][mrow];
            uint32_t a3l = apl[kr + tg + 4][mrow + 8];
#pragma unroll
            for (int jt = 0; jt < 8; jt++) {
                int col = wn * 64 + jt * 8 + g;
                uint32_t b0h = wph[kr + tg][col];
                uint32_t b1h = wph[kr + tg + 4][col];
                uint32_t b0l = wpl[kr + tg][col];
                uint32_t b1l = wpl[kr + tg + 4][col];
                mma_bf16(acc[jt], a0h, a1h, a2h, a3h, b0h, b1h);
                mma_bf16(acc[jt], a0h, a1h, a2h, a3h, b0l, b1l);
                mma_bf16(acc[jt], a0l, a1l, a2l, a3l, b0h, b1h);
            }
        }
    };

    load(k0);
    store(0);
    __syncthreads();
    for (int s = 0; s < nst; s++) {
        if (s + 1 < nst) load(k0 + (s + 1) * 32);
        compute(s & 1);
        if (s + 1 < nst) {
            store((s + 1) & 1);
            __syncthreads();
        }
    }

    // ---- write partials ----
#pragma unroll
    for (int jt = 0; jt < 8; jt++) {
        int col = n0 + wn * 64 + jt * 8 + tg * 2;
        int row0 = wm * 16 + g;
        *(float2*)(P + (size_t)row0 * j.N + col) = make_float2(acc[jt][0], acc[jt][1]);
        *(float2*)(P + (size_t)(row0 + 8) * j.N + col) = make_float2(acc[jt][2], acc[jt][3]);
    }
}

// ---------------- float4 split-K reduce + epilogue, dual-job ----------------
struct RJob {
    const float4* P; int np;
    const float4* bias; float4* C;
    int mode; const float4* R; int N4;
};

__global__ __launch_bounds__(256) void reduce_k(RJob r0, RJob r1) {
    RJob r = blockIdx.z ? r1 : r0;
    int idx = blockIdx.x * 256 + threadIdx.x;
    int total = 64 * r.N4;
    if (idx >= total) return;
    int n4 = idx % r.N4;
    float4 s = make_float4(0.f, 0.f, 0.f, 0.f);
#pragma unroll 4
    for (int p = 0; p < r.np; p++) {
        float4 v = r.P[(size_t)p * total + idx];
        s.x += v.x; s.y += v.y; s.z += v.z; s.w += v.w;
    }
    float4 b = r.bias[n4];
    s.x += b.x; s.y += b.y; s.z += b.z; s.w += b.w;
    if (r.mode == 1) {
        s.x = siluf_(s.x); s.y = siluf_(s.y); s.z = siluf_(s.z); s.w = siluf_(s.w);
    } else if (r.mode == 2) {
        s.x = sigmoidf_(s.x); s.y = sigmoidf_(s.y); s.z = sigmoidf_(s.z); s.w = sigmoidf_(s.w);
    } else if (r.mode == 3) {
        float4 rv = r.R[idx];
        s.x += rv.x; s.y += rv.y; s.z += rv.z; s.w += rv.w;
    }
    r.C[idx] = s;
}

// ---------------- block-diagonal q/k/v: tile 32(m) x 64(n), 128 thr ----------------
__global__ __launch_bounds__(128) void qkv_kernel(const float* __restrict__ Wq,
                                                  const float* __restrict__ Wk,
                                                  const float* __restrict__ Wv,
                                                  const float* __restrict__ bq,
                                                  const float* __restrict__ bk,
                                                  const float* __restrict__ bv) {
    int z = blockIdx.z;
    int which = z >> 3, h = z & 7;
    const float* A = (which == 2) ? g_xl : g_xc;
    const float* W; const float* bias; float* C; float scale = 1.f;
    if (which == 0) { W = Wq; bias = bq; C = g_q; }
    else if (which == 1) { W = Wk; bias = bk; C = g_k; scale = 0.0625f; }
    else { W = Wv; bias = bv; C = g_v; }
    W += (size_t)h * ND * ND;
    bias += h * ND;
    int n0 = blockIdx.x * 64;
    int m0 = blockIdx.y * 32;
    __shared__ __align__(16) float As[32][36];
    __shared__ __align__(16) float Ws[32][68];
    int tx = threadIdx.x & 15, ty = threadIdx.x >> 4;
    float acc[4][4] = {};
    for (int kb = 0; kb < ND; kb += 32) {
#pragma unroll
        for (int r = 0; r < 2; r++) {
            int ee = threadIdx.x + r * 128;
            int k4 = ee & 7, m = ee >> 3;
            float4 v = *(const float4*)(A + (size_t)(m0 + m) * NHID + h * ND + kb + 4 * k4);
            *(float4*)&As[m][4 * k4] = v;
        }
#pragma unroll
        for (int r = 0; r < 4; r++) {
            int ee = threadIdx.x + r * 128;
            int n4 = ee & 15, k = ee >> 4;
            float4 v = *(const float4*)(W + (size_t)(kb + k) * ND + n0 + 4 * n4);
            *(float4*)&Ws[k][4 * n4] = v;
        }
        __syncthreads();
#pragma unroll
        for (int kk = 0; kk < 32; kk++) {
            float4 w = *(const float4*)&Ws[kk][tx * 4];
            float a0 = As[ty * 4 + 0][kk];
            float a1 = As[ty * 4 + 1][kk];
            float a2 = As[ty * 4 + 2][kk];
            float a3 = As[ty * 4 + 3][kk];
            acc[0][0] += a0 * w.x; acc[0][1] += a0 * w.y; acc[0][2] += a0 * w.z; acc[0][3] += a0 * w.w;
            acc[1][0] += a1 * w.x; acc[1][1] += a1 * w.y; acc[1][2] += a1 * w.z; acc[1][3] += a1 * w.w;
            acc[2][0] += a2 * w.x; acc[2][1] += a2 * w.y; acc[2][2] += a2 * w.z; acc[2][3] += a2 * w.w;
            acc[3][0] += a3 * w.x; acc[3][1] += a3 * w.y; acc[3][2] += a3 * w.z; acc[3][3] += a3 * w.w;
        }
        __syncthreads();
    }
#pragma unroll
    for (int i = 0; i < 4; i++) {
        int m = m0 + ty * 4 + i;
        int n = n0 + tx * 4;
        float4 b4 = *(const float4*)(bias + n);
        float4 v = make_float4((acc[i][0] + b4.x) * scale, (acc[i][1] + b4.y) * scale,
                               (acc[i][2] + b4.z) * scale, (acc[i][3] + b4.w) * scale);
        *(float4*)(C + (size_t)m * NHID + h * ND + n) = v;
    }
}

// ---------------- i/f gate GEMVs + stabilized exp gating ----------------
__global__ __launch_bounds__(256) void gates_kernel(const float* __restrict__ Wi,
                                                    const float* __restrict__ bi,
                                                    const float* __restrict__ Wf,
                                                    const float* __restrict__ bf,
                                                    const float* __restrict__ m_prev,
                                                    float* __restrict__ m_out) {
    int b = blockIdx.x, t = threadIdx.x;
    float pi[8] = {}, pf[8] = {};
    for (int k = t; k < NHID; k += 256) {
        float xv = g_xc[b * NHID + k];
        const float4* wi4 = (const float4*)(Wi + k * 8);
        const float4* wf4 = (const float4*)(Wf + k * 8);
        float4 a0 = wi4[0], a1 = wi4[1], f0 = wf4[0], f1 = wf4[1];
        pi[0] += xv * a0.x; pi[1] += xv * a0.y; pi[2] += xv * a0.z; pi[3] += xv * a0.w;
        pi[4] += xv * a1.x; pi[5] += xv * a1.y; pi[6] += xv * a1.z; pi[7] += xv * a1.w;
        pf[0] += xv * f0.x; pf[1] += xv * f0.y; pf[2] += xv * f0.z; pf[3] += xv * f0.w;
        pf[4] += xv * f1.x; pf[5] += xv * f1.y; pf[6] += xv * f1.z; pf[7] += xv * f1.w;
    }
    __shared__ float s[256 * 16];
#pragma unroll
    for (int h = 0; h < 8; h++) { s[t * 16 + h] = pi[h]; s[t * 16 + 8 + h] = pf[h]; }
    __syncthreads();
    if (t < 16) {
        float a = 0.f;
        for (int r = 0; r < 256; r++) a += s[r * 16 + t];
        s[t] = a;
    }
    __syncthreads();
    if (t < 8) {
        float it = s[t] + bi[t];
        float ft = s[8 + t] + bf[t];
        float mp = m_prev[b * 8 + t];
        float m = fmaxf(ft + mp, it);
        m_out[b * 8 + t] = m;
        g_ig[b * 8 + t] = expf(it - m);
        g_fg[b * 8 + t] = expf(ft + mp - m);
    }
}

// ---------------- fused state update + readout + GroupNorm + gating ----------------
__global__ __launch_bounds__(256) void state_kernel(const float* __restrict__ c_prev,
                                                    const float* __restrict__ n_prev,
                                                    const float* __restrict__ gn_w,
                                                    const float* __restrict__ gn_b,
                                                    float* __restrict__ c_out,
                                                    float* __restrict__ n_out,
                                                    float* __restrict__ h_out) {
    int bh = blockIdx.x;
    int b = bh >> 3, h = bh & 7;
    int t = threadIdx.x;
    __shared__ __align__(16) float qs[256], ks[256], vs[256], hts[256];
    __shared__ float den_s;
    float fg = g_fg[bh], ig = g_ig[bh];
    int base = bh * ND;
    float qv = g_q[base + t], kv = g_k[base + t], vv = g_v[base + t];
    qs[t] = qv; ks[t] = kv; vs[t] = vv;
    float nt = fg * n_prev[base + t] + ig * kv;
    n_out[base + t] = nt;
    float den = blockReduce256(nt * qv);
    if (t == 0) den_s = fmaxf(den, 1.f);
    __syncthreads();
    den = den_s;
    int w = t >> 5, lane = t & 31;
    const float4* cp4 = (const float4*)(c_prev + (size_t)bh * ND * ND);
    float4* ct4 = (float4*)(c_out + (size_t)bh * ND * ND);
    const float4* qs4 = (const float4*)qs;
    const float4* ks4 = (const float4*)ks;
    for (int d0 = w * 32; d0 < w * 32 + 32; d0 += 4) {
        float acc0 = 0.f, acc1 = 0.f, acc2 = 0.f, acc3 = 0.f;
        float vd0 = vs[d0 + 0] * ig, vd1 = vs[d0 + 1] * ig;
        float vd2 = vs[d0 + 2] * ig, vd3 = vs[d0 + 3] * ig;
#pragma unroll
        for (int p = 0; p < 2; p++) {
            int ci = lane + p * 32;
            float4 kk = ks4[ci];
            float4 qq = qs4[ci];
            float4 cp0 = cp4[(size_t)(d0 + 0) * 64 + ci];
            float4 cp1 = cp4[(size_t)(d0 + 1) * 64 + ci];
            float4 cp2 = cp4[(size_t)(d0 + 2) * 64 + ci];
            float4 cp3 = cp4[(size_t)(d0 + 3) * 64 + ci];
            float4 c0, c1, c2, c3;
            c0.x = fg * cp0.x + vd0 * kk.x; c0.y = fg * cp0.y + vd0 * kk.y;
            c0.z = fg * cp0.z + vd0 * kk.z; c0.w = fg * cp0.w + vd0 * kk.w;
            c1.x = fg * cp1.x + vd1 * kk.x; c1.y = fg * cp1.y + vd1 * kk.y;
            c1.z = fg * cp1.z + vd1 * kk.z; c1.w = fg * cp1.w + vd1 * kk.w;
            c2.x = fg * cp2.x + vd2 * kk.x; c2.y = fg * cp2.y + vd2 * kk.y;
            c2.z = fg * cp2.z + vd2 * kk.z; c2.w = fg * cp2.w + vd2 * kk.w;
            c3.x = fg * cp3.x + vd3 * kk.x; c3.y = fg * cp3.y + vd3 * kk.y;
            c3.z = fg * cp3.z + vd3 * kk.z; c3.w = fg * cp3.w + vd3 * kk.w;
            ct4[(size_t)(d0 + 0) * 64 + ci] = c0;
            ct4[(size_t)(d0 + 1) * 64 + ci] = c1;
            ct4[(size_t)(d0 + 2) * 64 + ci] = c2;
            ct4[(size_t)(d0 + 3) * 64 + ci] = c3;
            acc0 += c0.x * qq.x + c0.y * qq.y + c0.z * qq.z + c0.w * qq.w;
            acc1 += c1.x * qq.x + c1.y * qq.y + c1.z * qq.z + c1.w * qq.w;
            acc2 += c2.x * qq.x + c2.y * qq.y + c2.z * qq.z + c2.w * qq.w;
            acc3 += c3.x * qq.x + c3.y * qq.y + c3.z * qq.z + c3.w * qq.w;
        }
#pragma unroll
        for (int off = 16; off > 0; off >>= 1) {
            acc0 += __shfl_xor_sync(0xffffffffu, acc0, off);
            acc1 += __shfl_xor_sync(0xffffffffu, acc1, off);
            acc2 += __shfl_xor_sync(0xffffffffu, acc2, off);
            acc3 += __shfl_xor_sync(0xffffffffu, acc3, off);
        }
        if (lane == 0) {
            float h0 = g_o[base + d0 + 0] * acc0 / den;
            float h1 = g_o[base + d0 + 1] * acc1 / den;
            float h2 = g_o[base + d0 + 2] * acc2 / den;
            float h3 = g_o[base + d0 + 3] * acc3 / den;
            hts[d0 + 0] = h0; hts[d0 + 1] = h1; hts[d0 + 2] = h2; hts[d0 + 3] = h3;
            h_out[base + d0 + 0] = h0; h_out[base + d0 + 1] = h1;
            h_out[base + d0 + 2] = h2; h_out[base + d0 + 3] = h3;
        }
    }
    __syncthreads();
    float hv = hts[t];
    float mu = blockReduce256(hv) * (1.f / ND);
    float dv = hv - mu;
    float var = blockReduce256(dv * dv) * (1.f / ND);
    float g = dv * rsqrtf(var + EPS);
    int hid = h * ND + t;
    float xrv = g_xr[b * NHID + hid];
    g_outpre[b * NHID + hid] =
        (g * gn_w[hid] + gn_b[hid] + g_xskip[b * NHID + hid]) * siluf_(xrv);
}

// ---------------- host launcher ----------------
extern "C" void kernel_launch(void* const* d_in, const int* in_sizes, int n_in,
                              void* d_out, int out_size) {
    (void)in_sizes; (void)n_in; (void)out_size;
    const float* x      = (const float*)d_in[0];
    const float* c_prev = (const float*)d_in[2];
    const float* n_prev = (const float*)d_in[3];
    const float* m_prev = (const float*)d_in[4];
    const float* ln_w   = (const float*)d_in[5];
    const float* ln_b   = (const float*)d_in[6];
    const float* W_ul   = (const float*)d_in[7];
    const float* b_ul   = (const float*)d_in[8];
    const float* W_ur   = (const float*)d_in[9];
    const float* b_ur   = (const float*)d_in[10];
    const float* W_conv = (const float*)d_in[11];
    const float* b_conv = (const float*)d_in[12];
    const float* W_skip = (const float*)d_in[13];
    const float* b_skip = (const float*)d_in[14];
    const float* W_q    = (const float*)d_in[15];
    const float* b_q    = (const float*)d_in[16];
    const float* W_k    = (const float*)d_in[17];
    const float* b_k    = (const float*)d_in[18];
    const float* W_v    = (const float*)d_in[19];
    const float* b_v    = (const float*)d_in[20];
    const float* W_i    = (const float*)d_in[21];
    const float* b_i    = (const float*)d_in[22];
    const float* W_f    = (const float*)d_in[23];
    const float* b_f    = (const float*)d_in[24];
    const float* W_o    = (const float*)d_in[25];
    const float* b_o    = (const float*)d_in[26];
    const float* W_down = (const float*)d_in[27];
    const float* b_down = (const float*)d_in[28];
    const float* gn_w   = (const float*)d_in[29];
    const float* gn_b   = (const float*)d_in[30];

    float* out = (float*)d_out;
    float* out_final = out;
    float* out_h = out + NB * NI;
    float* out_c = out_h + NB * NH * ND;
    float* out_n = out_c + (size_t)NB * NH * ND * ND;
    float* out_m = out_n + NB * NH * ND;

    void *p_xn, *p_xl, *p_xr, *p_xc, *p_xskip, *p_o, *p_outpre, *p_part, *p_wch, *p_wcl;
    cudaGetSymbolAddress(&p_xn, g_xn);
    cudaGetSymbolAddress(&p_xl, g_xl);
    cudaGetSymbolAddress(&p_xr, g_xr);
    cudaGetSymbolAddress(&p_xc, g_xc);
    cudaGetSymbolAddress(&p_xskip, g_xskip);
    cudaGetSymbolAddress(&p_o, g_o);
    cudaGetSymbolAddress(&p_outpre, g_outpre);
    cudaGetSymbolAddress(&p_part, g_part);
    cudaGetSymbolAddress(&p_wch, g_wch);
    cudaGetSymbolAddress(&p_wcl, g_wcl);
    float* xn = (float*)p_xn;
    float* xl = (float*)p_xl;
    float* xr = (float*)p_xr;
    float* xc = (float*)p_xc;
    float* xskip = (float*)p_xskip;
    float* o = (float*)p_o;
    float* outpre = (float*)p_outpre;
    float* part = (float*)p_part;
    const uint32_t* wch = (const uint32_t*)p_wch;
    const uint32_t* wcl = (const uint32_t*)p_wcl;

    const int SLOT = NB * NHID;
    const int SMEM_BYTES = SMEM_WORDS * 4;   // 53248
    cudaFuncSetAttribute(gemm_t, cudaFuncAttributeMaxDynamicSharedMemorySize, SMEM_BYTES);

    // 0. prepack conv tap-3 (no deps)
    prep_conv<<<dim3(64, 64), 256>>>(W_conv);

    // 1. LayerNorm
    ln_kernel<<<NB, 256>>>(x, ln_w, ln_b);

    // 2. xl / xr : K=1024, 8-way split
    {
        GJob a{xn, W_ul, nullptr, nullptr, part, NI, 128, NHID, 0};
        GJob b2{xn, W_ur, nullptr, nullptr, part + (size_t)8 * SLOT, NI, 128, NHID, 0};
        gemm_t<<<dim3(16, 8, 2), 256, SMEM_BYTES>>>(a, b2);
        RJob ra{(const float4*)part, 8, (const float4*)b_ul, (float4*)xl, 0, nullptr, NHID / 4};
        RJob rb{(const float4*)(part + (size_t)8 * SLOT), 8, (const float4*)b_ur, (float4*)xr, 0, nullptr, NHID / 4};
        reduce_k<<<dim3(128, 1, 2), 256>>>(ra, rb);
    }

    // 3. conv (prepacked bf16) + o-pre : K=2048, 8-way split
    {
        GJob a{xl, nullptr, wch, wcl, part, NHID, 256, NHID, 1};
        GJob b2{xl, W_o, nullptr, nullptr, part + (size_t)8 * SLOT, NHID, 256, NHID, 0};
        gemm_t<<<dim3(16, 8, 2), 256, SMEM_BYTES>>>(a, b2);
        RJob ra{(const float4*)part, 8, (const float4*)b_conv, (float4*)xc, 1, nullptr, NHID / 4};
        RJob rb{(const float4*)(part + (size_t)8 * SLOT), 8, (const float4*)b_o, (float4*)o, 2, nullptr, NHID / 4};
        reduce_k<<<dim3(128, 1, 2), 256>>>(ra, rb);
    }

    // 4. skip GEMM (16-way split) + qkv + gates
    {
        GJob a{xc, W_skip, nullptr, nullptr, part, NHID, 128, NHID, 0};
        gemm_t<<<dim3(16, 16, 1), 256, SMEM_BYTES>>>(a, a);
        qkv_kernel<<<dim3(4, 2, 24), 128>>>(W_q, W_k, W_v, b_q, b_k, b_v);
        gates_kernel<<<NB, 256>>>(W_i, b_i, W_f, b_f, m_prev, out_m);
        RJob ra{(const float4*)part, 16, (const float4*)b_skip, (float4*)xskip, 0, nullptr, NHID / 4};
        reduce_k<<<dim3(128, 1, 1), 256>>>(ra, ra);
    }

    // 5. fused state update / readout / groupnorm / gating
    state_kernel<<<NB * NH, 256>>>(c_prev, n_prev, gn_w, gn_b, out_c, out_n, out_h);

    // 6. final = outpre @ W_down + b_down + x : K=2048, 32-way split, N=1024
    {
        GJob a{outpre, W_down, nullptr, nullptr, part, NHID, 64, NI, 0};
        gemm_t<<<dim3(8, 32, 1), 256, SMEM_BYTES>>>(a, a);
        RJob ra{(const float4*)part, 32, (const float4*)b_down, (float4*)out_final, 3, (const float4*)x, NI / 4};
        reduce_k<<<dim3(64, 1, 1), 256>>>(ra, ra);
    }
}